// round 12
// baseline (speedup 1.0000x reference)
#include <cuda_runtime.h>
#include <cuda_bf16.h>
#include <cstdint>
#include <cstddef>

constexpr int Bn  = 512;
constexpr int QLn = 128;
constexpr int ALn = 512;
constexpr int Fn  = 400;
constexpr int Fp  = 512;
constexpr int EPW = 320;                 // e padded to 10*32 (emb row stride, floats)
constexpr int NS  = 10;
constexpr int NEMBP = 50001 * EPW;
// conv_a stage: W 1536 rows + X 4*258 rows (32B rows)
constexpr int NRA = 258;
constexpr int STAGE_A = (1536 + 4 * NRA) * 32;     // 82176 B
constexpr int SMEM_A2 = 2 * STAGE_A;               // 164352
// conv_q2 stage: W1 1536 + W2 1536 + X 4*130 rows
constexpr int NRQ = 130;
constexpr int STAGE_Q = (3072 + 4 * NRQ) * 32;     // 114944 B
constexpr int SMEM_Q2 = 2 * STAGE_Q;               // 229888

// ---------------- device scratch ----------------
__device__ __align__(256) float d_biasPad[Fp];
__device__ __align__(256) float d_b2[Fp];
__device__ __align__(256) float d_W32[3 * Fp * EPW];    // tf32 conv_w [j][f][e]
__device__ __align__(256) float d_W232[3 * Fp * EPW];   // tf32 U^T conv_w
__device__ __align__(256) float d_emb32[NEMBP];         // tf32 padded emb
__device__ __align__(256) float d_A[(size_t)Bn * Fn * ALn];
__device__ __align__(256) float d_Q[(size_t)Bn * Fn * QLn];
__device__ __align__(256) float d_tQ[(size_t)Bn * Fn * QLn];
__device__ __align__(256) float d_maxQp[Bn * 4 * QLn];
__device__ __align__(256) float d_maxA[Bn * ALn];

// ---------------- helpers ----------------
__device__ __forceinline__ float tanh_fast(float x) {
    float e = __expf(2.0f * x);
    return 1.0f - __fdividef(2.0f, e + 1.0f);
}
__device__ __forceinline__ uint32_t smem_u32(const void* p) {
    uint32_t a;
    asm("{ .reg .u64 t; cvta.to.shared.u64 t, %1; cvt.u32.u64 %0, t; }" : "=r"(a) : "l"(p));
    return a;
}
__device__ __forceinline__ float to_tf32(float x) {
    uint32_t r;
    asm("cvt.rna.tf32.f32 %0, %1;" : "=r"(r) : "f"(x));
    return __uint_as_float(r);
}
__device__ __forceinline__ uint32_t tf32_bits(float x) {
    uint32_t r;
    asm("cvt.rna.tf32.f32 %0, %1;" : "=r"(r) : "f"(x));
    return r;
}
__device__ __forceinline__ void mma_tf32(float* c, const uint32_t* a, uint32_t b0, uint32_t b1) {
    asm volatile(
        "mma.sync.aligned.m16n8k8.row.col.f32.tf32.tf32.f32 "
        "{%0,%1,%2,%3}, {%4,%5,%6,%7}, {%8,%9}, {%0,%1,%2,%3};"
        : "+f"(c[0]), "+f"(c[1]), "+f"(c[2]), "+f"(c[3])
        : "r"(a[0]), "r"(a[1]), "r"(a[2]), "r"(a[3]), "r"(b0), "r"(b1));
}
__device__ __forceinline__ void ldsm4(uint32_t* r, uint32_t addr) {
    asm volatile("ldmatrix.sync.aligned.m8n8.x4.shared.b16 {%0,%1,%2,%3}, [%4];"
        : "=r"(r[0]), "=r"(r[1]), "=r"(r[2]), "=r"(r[3]) : "r"(addr));
}
__device__ __forceinline__ void cp16(uint32_t dst, const void* src, uint32_t sz) {
    asm volatile("cp.async.cg.shared.global [%0], [%1], 16, %2;"
        :: "r"(dst), "l"(src), "r"(sz) : "memory");
}
__device__ __forceinline__ void sts128(uint32_t addr, uint32_t w0, uint32_t w1,
                                       uint32_t w2, uint32_t w3) {
    asm volatile("st.shared.v4.b32 [%0], {%1,%2,%3,%4};"
        :: "r"(addr), "r"(w0), "r"(w1), "r"(w2), "r"(w3));
}
// row-major tiles of 32B rows (2x16B chunks), chunk XOR swizzle
__device__ __forceinline__ uint32_t swaddr(uint32_t base, uint32_t row, uint32_t chunk) {
    return base + row * 32u + ((chunk ^ ((row >> 2) & 1u)) << 4);
}

// ---------------- prep kernels ----------------
__global__ void prep_w(const float* __restrict__ cw, const float* __restrict__ cb,
                       float* __restrict__ biasPad, float* __restrict__ W32) {
    int idx = blockIdx.x * 256 + threadIdx.x;
    if (idx < Fp) biasPad[idx] = (idx < Fn) ? cb[idx] : 0.0f;
    if (idx >= 3 * Fp * EPW) return;
    int j = idx / (Fp * EPW), rem = idx - j * (Fp * EPW);
    int f = rem / EPW, e = rem - f * EPW;
    float v = 0.0f;
    if (f < Fn && e < 300) v = cw[(f * 300 + e) * 3 + j];
    W32[idx] = to_tf32(v);
}

__global__ void prep_w2(const float* __restrict__ U, const float* __restrict__ cb,
                        const float* __restrict__ cw, float* __restrict__ b2,
                        float* __restrict__ W232) {
    int idx = blockIdx.x * 256 + threadIdx.x;
    if (idx < Fp) {
        float a = 0.0f;
        if (idx < Fn) for (int f = 0; f < Fn; f++) a += U[f * Fn + idx] * cb[f];
        b2[idx] = a;
    }
    if (idx >= 3 * Fp * EPW) return;
    int j = idx / (Fp * EPW), rem = idx - j * (Fp * EPW);
    int g = rem / EPW, e = rem - g * EPW;
    float a = 0.0f;
    if (g < Fn && e < 300) {
#pragma unroll 4
        for (int f = 0; f < Fn; f++) a += U[f * Fn + g] * cw[(f * 300 + e) * 3 + j];
    }
    W232[idx] = to_tf32(a);
}

__global__ void emb_cvt(const float* __restrict__ emb, float* __restrict__ e32) {
    int idx = blockIdx.x * 256 + threadIdx.x;
    if (idx >= NEMBP) return;
    int t = idx / EPW, e = idx - t * EPW;
    float v = (e < 300) ? emb[(size_t)t * 300 + e] : 0.0f;
    e32[idx] = to_tf32(v);
}

// ---------------- fill pieces (256 threads), e-chunk = 32 ----------------
// W rows: jsub = j*4 + sub (sub = k-subchunk of 8), f = row & 127; 1536 rows.
__device__ __forceinline__ void fill_w(
    uint32_t stage, uint32_t rowOff, int e0, int tid, int fBase,
    const float* __restrict__ W) {
#pragma unroll
    for (int it = 0; it < 12; it++) {
        int idx = it * 256 + tid;
        uint32_t row = (uint32_t)idx >> 1, chunk = idx & 1;
        uint32_t jsub = row >> 7, f = row & 127u;
        const float* src = W + ((size_t)(jsub >> 2) * Fp + fBase + f) * EPW
                         + e0 + (jsub & 3) * 8 + chunk * 4;
        cp16(swaddr(stage, rowOff + row, chunk), src, (fBase + (int)f < Fn) ? 16u : 0u);
    }
}

template <int NR>   // rows per sub-table
__device__ __forceinline__ void fill_x(
    uint32_t stage, uint32_t rowOff, int e0, int tid,
    const float* __restrict__ e32, const int* stok) {
    constexpr int NCH = NR * 8;   // 4 subchunks x 2 chunks x NR rows
#pragma unroll
    for (int it = 0; it < (NCH + 255) / 256; it++) {
        int idx = it * 256 + tid;
        if (idx < NCH) {
            uint32_t sub = (uint32_t)idx / (NR * 2);
            uint32_t rem = (uint32_t)idx - sub * (NR * 2);
            uint32_t r = rem >> 1, chunk = rem & 1;
            int t = stok[r];
            const float* src = e32 + (size_t)(t < 0 ? 0 : t) * EPW
                             + e0 + sub * 8 + chunk * 4;
            cp16(swaddr(stage, rowOff + sub * (uint32_t)NR + r, chunk), src,
                 (t < 0) ? 0u : 16u);
        }
    }
}

// ---------------- 64x64-warp tf32 compute stage (e=32) ----------------
__device__ __forceinline__ void conv_cs64(
    uint32_t stg, int lane, uint32_t wRowBase, uint32_t xRowBase, uint32_t NRtab,
    float acc[4][8][4]) {
    const uint32_t frA = (((uint32_t)lane >> 3) & 1u) * 8u + ((uint32_t)lane & 7u);
    const uint32_t chA = (uint32_t)lane >> 4;
    const uint32_t frB = (((uint32_t)lane >> 4) << 3) + ((uint32_t)lane & 7u);
    const uint32_t chB = ((uint32_t)lane >> 3) & 1u;
#pragma unroll
    for (int j = 0; j < 3; j++) {
#pragma unroll
        for (int sub = 0; sub < 4; sub++) {
            uint32_t a[4][4], bq[16];
#pragma unroll
            for (int mt = 0; mt < 4; mt++) {
                uint32_t rowA = wRowBase + (uint32_t)(j * 512 + sub * 128 + mt * 16) + frA;
                ldsm4(a[mt], swaddr(stg, rowA, chA));
            }
#pragma unroll
            for (int p = 0; p < 4; p++) {
                uint32_t rowB = xRowBase + sub * NRtab + (uint32_t)(p * 16) + frB + (uint32_t)j;
                ldsm4(bq + 4 * p, swaddr(stg, rowB, chB));
            }
#pragma unroll
            for (int mt = 0; mt < 4; mt++)
#pragma unroll
                for (int nt = 0; nt < 8; nt++)
                    mma_tf32(acc[mt][nt], a[mt], bq[2 * nt], bq[2 * nt + 1]);
        }
    }
}

__device__ __forceinline__ void conv_epi64(
    float acc[4][8][4], int fBase64, int lBase64, int lane,
    const float* __restrict__ bias, float* __restrict__ out, int L, int b) {
    const int r4 = lane & 3, q = lane >> 2;
#pragma unroll
    for (int mt = 0; mt < 4; mt++) {
        int f0 = fBase64 + mt * 16 + q;
        float bv0 = (f0 < Fn) ? bias[f0] : 0.0f;
        float bv1 = (f0 + 8 < Fn) ? bias[f0 + 8] : 0.0f;
#pragma unroll
        for (int nt = 0; nt < 8; nt++) {
            int l = lBase64 + nt * 8 + r4 * 2;
            if (f0 < Fn) {
                float2 v = make_float2(acc[mt][nt][0] + bv0, acc[mt][nt][1] + bv0);
                *(float2*)(out + ((size_t)b * Fn + f0) * L + l) = v;
            }
            if (f0 + 8 < Fn) {
                float2 v = make_float2(acc[mt][nt][2] + bv1, acc[mt][nt][3] + bv1);
                *(float2*)(out + ((size_t)b * Fn + f0 + 8) * L + l) = v;
            }
        }
    }
}

// ---------------- A conv: tile 128f x 256l, 8 warps of 64x64 ----------------
__global__ void __launch_bounds__(256, 1)
conv_a(const int* __restrict__ tok, int L,
       const float* __restrict__ e32, const float* __restrict__ W,
       const float* __restrict__ bias, float* __restrict__ out) {
    extern __shared__ uint32_t dsm[];
    __shared__ int stok[NRA];

    const int tid = threadIdx.x;
    const int wid = tid >> 5, lane = tid & 31;
    const int wm = wid & 1, wn = wid >> 1;       // 2f x 4l
    const int lBase = blockIdx.x * 256;
    const int fBase = blockIdx.y * 128;
    const int b = blockIdx.z;
    const bool fvalid = (fBase + wm * 64) < Fn;
    const uint32_t sbase = smem_u32(dsm);

    for (int i = tid; i < NRA; i += 256) {
        int pos = lBase + i - 1;
        stok[i] = (pos >= 0 && pos < L) ? tok[b * L + pos] : -1;
    }
    __syncthreads();

    float acc[4][8][4];
#pragma unroll
    for (int mt = 0; mt < 4; mt++)
#pragma unroll
        for (int nt = 0; nt < 8; nt++)
#pragma unroll
            for (int i = 0; i < 4; i++) acc[mt][nt][i] = 0.0f;

    fill_w(sbase, 0u, 0, tid, fBase, W);
    fill_x<NRA>(sbase, 1536u, 0, tid, e32, stok);
    asm volatile("cp.async.commit_group;" ::: "memory");

    for (int s = 0; s < NS; s++) {
        asm volatile("cp.async.wait_group 0;" ::: "memory");
        __syncthreads();
        if (s + 1 < NS) {
            uint32_t stg2 = sbase + (uint32_t)((s + 1) & 1) * STAGE_A;
            fill_w(stg2, 0u, (s + 1) * 32, tid, fBase, W);
            fill_x<NRA>(stg2, 1536u, (s + 1) * 32, tid, e32, stok);
            asm volatile("cp.async.commit_group;" ::: "memory");
        }
        const uint32_t stg = sbase + (uint32_t)(s & 1) * STAGE_A;
        if (fvalid)
            conv_cs64(stg, lane, (uint32_t)(wm * 64), 1536u + (uint32_t)(wn * 64),
                      (uint32_t)NRA, acc);
    }
    if (fvalid)
        conv_epi64(acc, fBase + wm * 64, lBase + wn * 64, lane, bias, out, L, b);
}

// ---------------- fused Q + tQ conv: tile 128f x 128l, shared X ----------------
__global__ void __launch_bounds__(256, 1)
conv_q2(const int* __restrict__ tok,
        const float* __restrict__ e32,
        const float* __restrict__ W1, const float* __restrict__ W2,
        const float* __restrict__ bias1, const float* __restrict__ bias2,
        float* __restrict__ out1, float* __restrict__ out2) {
    extern __shared__ uint32_t dsm[];
    __shared__ int stok[NRQ];

    const int tid = threadIdx.x;
    const int wid = tid >> 5, lane = tid & 31;
    const int ws = wid >> 2;                      // weight set 0 (Q) / 1 (tQ)
    const int wm = wid & 1, wn = (wid >> 1) & 1;  // 2f x 2l of 64x64
    const int fBase = blockIdx.y * 128;
    const int b = blockIdx.z;
    const bool fvalid = (fBase + wm * 64) < Fn;
    const uint32_t sbase = smem_u32(dsm);

    if (tid < NRQ) {
        int pos = tid - 1;
        stok[tid] = (pos >= 0 && pos < QLn) ? tok[b * QLn + pos] : -1;
    }
    __syncthreads();

    float acc[4][8][4];
#pragma unroll
    for (int mt = 0; mt < 4; mt++)
#pragma unroll
        for (int nt = 0; nt < 8; nt++)
#pragma unroll
            for (int i = 0; i < 4; i++) acc[mt][nt][i] = 0.0f;

    fill_w(sbase, 0u, 0, tid, fBase, W1);
    fill_w(sbase, 1536u, 0, tid, fBase, W2);
    fill_x<NRQ>(sbase, 3072u, 0, tid, e32, stok);
    asm volatile("cp.async.commit_group;" ::: "memory");

    for (int s = 0; s < NS; s++) {
        asm volatile("cp.async.wait_group 0;" ::: "memory");
        __syncthreads();
        if (s + 1 < NS) {
            uint32_t stg2 = sbase + (uint32_t)((s + 1) & 1) * STAGE_Q;
            fill_w(stg2, 0u, (s + 1) * 32, tid, fBase, W1);
            fill_w(stg2, 1536u, (s + 1) * 32, tid, fBase, W2);
            fill_x<NRQ>(stg2, 3072u, (s + 1) * 32, tid, e32, stok);
            asm volatile("cp.async.commit_group;" ::: "memory");
        }
        const uint32_t stg = sbase + (uint32_t)(s & 1) * STAGE_Q;
        if (fvalid)
            conv_cs64(stg, lane, (uint32_t)(ws * 1536 + wm * 64),
                      3072u + (uint32_t)(wn * 64), (uint32_t)NRQ, acc);
    }
    if (fvalid) {
        const float* bias = ws ? bias2 : bias1;
        float* out = ws ? out2 : out1;
        conv_epi64(acc, fBase + wm * 64, wn * 64, lane, bias, out, QLn, b);
    }
}

// ---------------- tf32 G-tile kernel ----------------
__global__ void __launch_bounds__(256)
g_mma(const float* __restrict__ tQ, const float* __restrict__ A,
      float* __restrict__ maxQp, float* __restrict__ maxA) {
    __shared__ __align__(16) uint32_t stg[4096];  // 16 KB
    __shared__ float sRow[2][128];
    __shared__ float sCol[4][128];

    const int tid = threadIdx.x;
    const int wid = tid >> 5, lane = tid & 31;
    const int wmf = wid & 3, wnf = wid >> 2;
    const int r4 = lane & 3, q8 = lane >> 2;
    const int at = blockIdx.x, b = blockIdx.y;

    const float* tqb = tQ + (size_t)b * Fn * QLn;
    const float* ab  = A  + (size_t)b * Fn * ALn + at * 128;
    const int role = tid >> 7;
    const int rrow = tid & 127;
    const float* src = role ? (ab + rrow) : (tqb + rrow);
    const int sstr = role ? ALn : QLn;
    const uint32_t sb = smem_u32(stg);

    const uint32_t frA = (((uint32_t)lane >> 3) & 1u) * 8u + ((uint32_t)lane & 7u);
    const uint32_t chA = (uint32_t)lane >> 4;
    const uint32_t frB = (((uint32_t)lane >> 4) << 3) + ((uint32_t)lane & 7u);
    const uint32_t chB = ((uint32_t)lane >> 3) & 1u;

    float acc[2][8][4];
#pragma unroll
    for (int mt = 0; mt < 2; mt++)
#pragma unroll
        for (int nt = 0; nt < 8; nt++)
#pragma unroll
            for (int i = 0; i < 4; i++) acc[mt][nt][i] = 0.0f;

    float v[16];
#pragma unroll
    for (int i = 0; i < 16; i++) v[i] = src[(size_t)i * sstr];

    for (int s = 0; s < 25; s++) {
        uint32_t w[16];
#pragma unroll
        for (int i = 0; i < 16; i++) w[i] = tf32_bits(v[i]);
        uint32_t rowS = (uint32_t)(role * 256 + rrow);
        sts128(swaddr(sb, rowS, 0), w[0], w[1], w[2], w[3]);
        sts128(swaddr(sb, rowS, 1), w[4], w[5], w[6], w[7]);
        sts128(swaddr(sb, rowS + 128u, 0), w[8], w[9], w[10], w[11]);
        sts128(swaddr(sb, rowS + 128u, 1), w[12], w[13], w[14], w[15]);
        __syncthreads();
        if (s < 24) {
            const float* s2 = src + (size_t)(s + 1) * 16 * sstr;
#pragma unroll
            for (int i = 0; i < 16; i++) v[i] = s2[(size_t)i * sstr];
        }
#pragma unroll
        for (int sub = 0; sub < 2; sub++) {
            uint32_t a0[4], a1[4], bq[16];
            uint32_t rowA = (uint32_t)(sub * 128 + wmf * 32) + frA;
            ldsm4(a0, swaddr(sb, rowA, chA));
            ldsm4(a1, swaddr(sb, rowA + 16u, chA));
#pragma unroll
            for (int p = 0; p < 4; p++) {
                uint32_t rowB = 256u + (uint32_t)(sub * 128 + wnf * 64 + p * 16) + frB;
                ldsm4(bq + 4 * p, swaddr(sb, rowB, chB));
            }
#pragma unroll
            for (int nt = 0; nt < 8; nt++) {
                mma_tf32(acc[0][nt], a0, bq[2 * nt], bq[2 * nt + 1]);
                mma_tf32(acc[1][nt], a1, bq[2 * nt], bq[2 * nt + 1]);
            }
        }
        __syncthreads();
    }

#pragma unroll
    for (int mt = 0; mt < 2; mt++)
#pragma unroll
        for (int nt = 0; nt < 8; nt++)
#pragma unroll
            for (int ci = 0; ci < 4; ci++)
                acc[mt][nt][ci] = tanh_fast(acc[mt][nt][ci]);

    float rm[4] = {-2.f, -2.f, -2.f, -2.f};
    float cm[16];
#pragma unroll
    for (int i = 0; i < 16; i++) cm[i] = -2.f;
#pragma unroll
    for (int mt = 0; mt < 2; mt++)
#pragma unroll
        for (int nt = 0; nt < 8; nt++)
#pragma unroll
            for (int ci = 0; ci < 4; ci++) {
                float g = acc[mt][nt][ci];
                rm[mt * 2 + (ci >> 1)] = fmaxf(rm[mt * 2 + (ci >> 1)], g);
                cm[nt * 2 + (ci & 1)] = fmaxf(cm[nt * 2 + (ci & 1)], g);
            }
#pragma unroll
    for (int k = 0; k < 4; k++) {
        rm[k] = fmaxf(rm[k], __shfl_xor_sync(0xffffffffu, rm[k], 1));
        rm[k] = fmaxf(rm[k], __shfl_xor_sync(0xffffffffu, rm[k], 2));
    }
#pragma unroll
    for (int k = 0; k < 16; k++) {
        cm[k] = fmaxf(cm[k], __shfl_xor_sync(0xffffffffu, cm[k], 4));
        cm[k] = fmaxf(cm[k], __shfl_xor_sync(0xffffffffu, cm[k], 8));
        cm[k] = fmaxf(cm[k], __shfl_xor_sync(0xffffffffu, cm[k], 16));
    }
    if (r4 == 0) {
#pragma unroll
        for (int mt = 0; mt < 2; mt++)
#pragma unroll
            for (int h = 0; h < 2; h++)
                sRow[wnf][wmf * 32 + mt * 16 + h * 8 + q8] = rm[mt * 2 + h];
    }
    if (q8 == 0) {
#pragma unroll
        for (int nt = 0; nt < 8; nt++)
#pragma unroll
            for (int c = 0; c < 2; c++)
                sCol[wmf][wnf * 64 + nt * 8 + r4 * 2 + c] = cm[nt * 2 + c];
    }
    __syncthreads();
    if (tid < 128) {
        maxQp[((size_t)b * 4 + at) * QLn + tid] = fmaxf(sRow[0][tid], sRow[1][tid]);
        float m = fmaxf(fmaxf(sCol[0][tid], sCol[1][tid]), fmaxf(sCol[2][tid], sCol[3][tid]));
        maxA[(size_t)b * ALn + at * 128 + tid] = m;
    }
}

// ---------------- finalize ----------------
__device__ __forceinline__ float blkReduce(float v, bool domax) {
    __shared__ float sb[8];
#pragma unroll
    for (int o = 16; o; o >>= 1) {
        float ov = __shfl_xor_sync(0xffffffffu, v, o);
        v = domax ? fmaxf(v, ov) : v + ov;
    }
    __syncthreads();
    if ((threadIdx.x & 31) == 0) sb[threadIdx.x >> 5] = v;
    __syncthreads();
    float r = sb[0];
#pragma unroll
    for (int w = 1; w < 8; w++) r = domax ? fmaxf(r, sb[w]) : r + sb[w];
    return r;
}

__global__ void __launch_bounds__(256)
final_kernel(const float* __restrict__ Q, const float* __restrict__ A,
             const float* __restrict__ maxQp, const float* __restrict__ maxA,
             float* __restrict__ out) {
    __shared__ float roQ[QLn];
    __shared__ float roA[ALn];
    __shared__ float rQ[Fn];
    __shared__ float rA[Fn];
    const int b = blockIdx.x, tid = threadIdx.x;

    float v = -2.0f;
    if (tid < QLn) {
        const float* mp = maxQp + (size_t)b * 4 * QLn + tid;
        v = fmaxf(fmaxf(mp[0], mp[QLn]), fmaxf(mp[2 * QLn], mp[3 * QLn]));
    }
    float m = blkReduce(v, true);
    float e = (tid < QLn) ? __expf(v - m) : 0.0f;
    float s = blkReduce(e, false);
    if (tid < QLn) roQ[tid] = e / s;

    float v0 = maxA[(size_t)b * ALn + tid];
    float v1 = maxA[(size_t)b * ALn + 256 + tid];
    m = blkReduce(fmaxf(v0, v1), true);
    float e0 = __expf(v0 - m), e1 = __expf(v1 - m);
    s = blkReduce(e0 + e1, false);
    roA[tid] = e0 / s;
    roA[tid + 256] = e1 / s;
    __syncthreads();

    for (int f = tid; f < Fn; f += 256) {
        const float4* qr = (const float4*)(Q + ((size_t)b * Fn + f) * QLn);
        float a = 0.0f;
#pragma unroll 8
        for (int c = 0; c < QLn / 4; c++) {
            float4 qv = qr[c];
            const float* w = &roQ[c * 4];
            a += qv.x * w[0] + qv.y * w[1] + qv.z * w[2] + qv.w * w[3];
        }
        rQ[f] = a;
    }
    for (int f = tid; f < Fn; f += 256) {
        const float4* ar = (const float4*)(A + ((size_t)b * Fn + f) * ALn);
        float a = 0.0f;
#pragma unroll 8
        for (int c = 0; c < ALn / 4; c++) {
            float4 qv = ar[c];
            const float* w = &roA[c * 4];
            a += qv.x * w[0] + qv.y * w[1] + qv.z * w[2] + qv.w * w[3];
        }
        rA[f] = a;
    }
    __syncthreads();

    float d = 0.0f, qq = 0.0f, aa = 0.0f;
    for (int f = tid; f < Fn; f += 256) {
        float x = rQ[f], y = rA[f];
        d += x * y; qq += x * x; aa += y * y;
    }
    d = blkReduce(d, false);
    qq = blkReduce(qq, false);
    aa = blkReduce(aa, false);
    if (tid == 0)
        out[b] = d / (fmaxf(sqrtf(qq), 1e-8f) * fmaxf(sqrtf(aa), 1e-8f));
}

// ---------------- launch ----------------
extern "C" void kernel_launch(void* const* d_in, const int* in_sizes, int n_in,
                              void* d_out, int out_size) {
    const int*   question = (const int*)d_in[0];
    const int*   answer   = (const int*)d_in[1];
    const float* emb      = (const float*)d_in[2];
    const float* conv_w   = (const float*)d_in[3];
    const float* conv_b   = (const float*)d_in[4];
    const float* U        = (const float*)d_in[5];
    float* out = (float*)d_out;

    float *biasPad, *b2, *W32, *W232, *e32, *Ac, *Qc, *tQc, *maxQp, *maxA;
    cudaGetSymbolAddress((void**)&biasPad, d_biasPad);
    cudaGetSymbolAddress((void**)&b2,      d_b2);
    cudaGetSymbolAddress((void**)&W32,     d_W32);
    cudaGetSymbolAddress((void**)&W232,    d_W232);
    cudaGetSymbolAddress((void**)&e32,     d_emb32);
    cudaGetSymbolAddress((void**)&Ac,      d_A);
    cudaGetSymbolAddress((void**)&Qc,      d_Q);
    cudaGetSymbolAddress((void**)&tQc,     d_tQ);
    cudaGetSymbolAddress((void**)&maxQp,   d_maxQp);
    cudaGetSymbolAddress((void**)&maxA,    d_maxA);

    cudaFuncSetAttribute(conv_a,  cudaFuncAttributeMaxDynamicSharedMemorySize, SMEM_A2);
    cudaFuncSetAttribute(conv_q2, cudaFuncAttributeMaxDynamicSharedMemorySize, SMEM_Q2);

    const int prepBlocks = (3 * Fp * EPW + 255) / 256;
    prep_w<<<prepBlocks, 256>>>(conv_w, conv_b, biasPad, W32);
    prep_w2<<<prepBlocks, 256>>>(U, conv_b, conv_w, b2, W232);
    emb_cvt<<<(NEMBP + 255) / 256, 256>>>(emb, e32);

    dim3 gA(ALn / 256, Fp / 128, Bn);   // (2, 4, 512)
    conv_a<<<gA, 256, SMEM_A2>>>(answer, ALn, e32, W32, biasPad, Ac);
    dim3 gQ(1, Fp / 128, Bn);           // (1, 4, 512)
    conv_q2<<<gQ, 256, SMEM_Q2>>>(question, e32, W32, W232, biasPad, b2, Qc, tQc);

    dim3 gG(4, Bn);
    g_mma<<<gG, 256>>>(tQc, Ac, maxQp, maxA);
    final_kernel<<<Bn, 256>>>(Qc, Ac, maxQp, maxA, out);
}

// round 13
// speedup vs baseline: 1.0539x; 1.0539x over previous
#include <cuda_runtime.h>
#include <cstdint>
#include <cstddef>

constexpr int Bn  = 512;
constexpr int QLn = 128;
constexpr int ALn = 512;
constexpr int Fn  = 400;
constexpr int Fp  = 512;
constexpr int EPW = 304;                 // e padded to 19*16 (emb row stride, floats)
constexpr int NS  = 19;
constexpr int NEMBP = 50001 * EPW;
constexpr int NBUF = 3;
constexpr int STAGE_A = (768 + 520) * 32;          // 41216 B
constexpr int STAGE_Q = (768 + 768 + 264) * 32;    // 57600 B
constexpr int SMEM_ALL = NBUF * STAGE_Q;           // 172800 (max of both paths)

// ---------------- device scratch ----------------
__device__ __align__(256) float d_biasPad[Fp];
__device__ __align__(256) float d_b2[Fp];
__device__ __align__(256) float d_W32[3 * Fp * EPW];    // tf32 conv_w [j][f][e]
__device__ __align__(256) float d_W232[3 * Fp * EPW];   // tf32 U^T conv_w
__device__ __align__(256) float d_emb32[NEMBP];         // tf32 padded emb
__device__ __align__(256) float d_A[(size_t)Bn * Fn * ALn];
__device__ __align__(256) float d_Q[(size_t)Bn * Fn * QLn];
__device__ __align__(256) float d_tQ[(size_t)Bn * Fn * QLn];
__device__ __align__(256) float d_maxQp[Bn * 4 * QLn];
__device__ __align__(256) float d_maxA[Bn * ALn];

// ---------------- helpers ----------------
__device__ __forceinline__ float tanh_fast(float x) {
    float e = __expf(2.0f * x);
    return 1.0f - __fdividef(2.0f, e + 1.0f);
}
__device__ __forceinline__ uint32_t smem_u32(const void* p) {
    uint32_t a;
    asm("{ .reg .u64 t; cvta.to.shared.u64 t, %1; cvt.u32.u64 %0, t; }" : "=r"(a) : "l"(p));
    return a;
}
__device__ __forceinline__ float to_tf32(float x) {
    uint32_t r;
    asm("cvt.rna.tf32.f32 %0, %1;" : "=r"(r) : "f"(x));
    return __uint_as_float(r);
}
__device__ __forceinline__ uint32_t tf32_bits(float x) {
    uint32_t r;
    asm("cvt.rna.tf32.f32 %0, %1;" : "=r"(r) : "f"(x));
    return r;
}
__device__ __forceinline__ void mma_tf32(float* c, const uint32_t* a, uint32_t b0, uint32_t b1) {
    asm volatile(
        "mma.sync.aligned.m16n8k8.row.col.f32.tf32.tf32.f32 "
        "{%0,%1,%2,%3}, {%4,%5,%6,%7}, {%8,%9}, {%0,%1,%2,%3};"
        : "+f"(c[0]), "+f"(c[1]), "+f"(c[2]), "+f"(c[3])
        : "r"(a[0]), "r"(a[1]), "r"(a[2]), "r"(a[3]), "r"(b0), "r"(b1));
}
__device__ __forceinline__ void ldsm4(uint32_t* r, uint32_t addr) {
    asm volatile("ldmatrix.sync.aligned.m8n8.x4.shared.b16 {%0,%1,%2,%3}, [%4];"
        : "=r"(r[0]), "=r"(r[1]), "=r"(r[2]), "=r"(r[3]) : "r"(addr));
}
__device__ __forceinline__ void cp16(uint32_t dst, const void* src, uint32_t sz) {
    asm volatile("cp.async.cg.shared.global [%0], [%1], 16, %2;"
        :: "r"(dst), "l"(src), "r"(sz) : "memory");
}
__device__ __forceinline__ void sts128(uint32_t addr, uint32_t w0, uint32_t w1,
                                       uint32_t w2, uint32_t w3) {
    asm volatile("st.shared.v4.b32 [%0], {%1,%2,%3,%4};"
        :: "r"(addr), "r"(w0), "r"(w1), "r"(w2), "r"(w3));
}
// row-major tiles of 32B rows (2x16B chunks), chunk XOR swizzle
__device__ __forceinline__ uint32_t swaddr(uint32_t base, uint32_t row, uint32_t chunk) {
    return base + row * 32u + ((chunk ^ ((row >> 2) & 1u)) << 4);
}

// ---------------- prep kernels ----------------
__global__ void prep_w(const float* __restrict__ cw, const float* __restrict__ cb,
                       float* __restrict__ biasPad, float* __restrict__ W32) {
    int idx = blockIdx.x * 256 + threadIdx.x;
    if (idx < Fp) biasPad[idx] = (idx < Fn) ? cb[idx] : 0.0f;
    if (idx >= 3 * Fp * EPW) return;
    int j = idx / (Fp * EPW), rem = idx - j * (Fp * EPW);
    int f = rem / EPW, e = rem - f * EPW;
    float v = 0.0f;
    if (f < Fn && e < 300) v = cw[(f * 300 + e) * 3 + j];
    W32[idx] = to_tf32(v);
}

__global__ void prep_w2(const float* __restrict__ U, const float* __restrict__ cb,
                        const float* __restrict__ cw, float* __restrict__ b2,
                        float* __restrict__ W232) {
    int idx = blockIdx.x * 256 + threadIdx.x;
    if (idx < Fp) {
        float a = 0.0f;
        if (idx < Fn) for (int f = 0; f < Fn; f++) a += U[f * Fn + idx] * cb[f];
        b2[idx] = a;
    }
    if (idx >= 3 * Fp * EPW) return;
    int j = idx / (Fp * EPW), rem = idx - j * (Fp * EPW);
    int g = rem / EPW, e = rem - g * EPW;
    float a = 0.0f;
    if (g < Fn && e < 300) {
#pragma unroll 4
        for (int f = 0; f < Fn; f++) a += U[f * Fn + g] * cw[(f * 300 + e) * 3 + j];
    }
    W232[idx] = to_tf32(a);
}

__global__ void emb_cvt(const float* __restrict__ emb, float* __restrict__ e32) {
    int idx = blockIdx.x * 256 + threadIdx.x;
    if (idx >= NEMBP) return;
    int t = idx / EPW, e = idx - t * EPW;
    float v = (e < 300) ? emb[(size_t)t * 300 + e] : 0.0f;
    e32[idx] = to_tf32(v);
}

// ---------------- fill pieces (256 threads), e-chunk = 16 ----------------
__device__ __forceinline__ void fill_w(
    uint32_t stage, uint32_t rowOff, int e0, int tid, int fBase,
    const float* __restrict__ W) {
#pragma unroll
    for (int it = 0; it < 6; it++) {
        int idx = it * 256 + tid;
        uint32_t row = (uint32_t)idx >> 1, chunk = idx & 1;
        uint32_t j2 = row >> 7, f = row & 127u;
        const float* src = W + ((size_t)(j2 >> 1) * Fp + fBase + f) * EPW
                         + e0 + (j2 & 1) * 8 + chunk * 4;
        cp16(swaddr(stage, rowOff + row, chunk), src, (fBase + (int)f < Fn) ? 16u : 0u);
    }
}

template <int NR>   // rows per sub-table
__device__ __forceinline__ void fill_x(
    uint32_t stage, uint32_t rowOff, int e0, int tid,
    const float* __restrict__ e32, const int* stok) {
    constexpr int NCH = NR * 4;   // 2 subchunks x 2 chunks x NR rows
#pragma unroll
    for (int it = 0; it < (NCH + 255) / 256; it++) {
        int idx = it * 256 + tid;
        if (idx < NCH) {
            uint32_t sub = (idx >= NR * 2) ? 1u : 0u;
            uint32_t rem = idx - sub * (NR * 2);
            uint32_t r = rem >> 1, chunk = rem & 1;
            int t = stok[r];
            const float* src = e32 + (size_t)(t < 0 ? 0 : t) * EPW
                             + e0 + sub * 8 + chunk * 4;
            cp16(swaddr(stage, rowOff + sub * (uint32_t)NR + r, chunk), src,
                 (t < 0) ? 0u : 16u);
        }
    }
}

// ---------------- 64x64-warp tf32 compute stage (e=16) ----------------
__device__ __forceinline__ void conv_cs64(
    uint32_t stg, int lane, uint32_t wRowBase, uint32_t xRowBase, uint32_t NRtab,
    float acc[4][8][4]) {
    const uint32_t frA = (((uint32_t)lane >> 3) & 1u) * 8u + ((uint32_t)lane & 7u);
    const uint32_t chA = (uint32_t)lane >> 4;
    const uint32_t frB = (((uint32_t)lane >> 4) << 3) + ((uint32_t)lane & 7u);
    const uint32_t chB = ((uint32_t)lane >> 3) & 1u;
#pragma unroll
    for (int j = 0; j < 3; j++) {
#pragma unroll
        for (int sub = 0; sub < 2; sub++) {
            uint32_t a[4][4], bq[16];
#pragma unroll
            for (int mt = 0; mt < 4; mt++) {
                uint32_t rowA = wRowBase + (uint32_t)(j * 256 + sub * 128 + mt * 16) + frA;
                ldsm4(a[mt], swaddr(stg, rowA, chA));
            }
#pragma unroll
            for (int p = 0; p < 4; p++) {
                uint32_t rowB = xRowBase + sub * NRtab + (uint32_t)(p * 16) + frB + (uint32_t)j;
                ldsm4(bq + 4 * p, swaddr(stg, rowB, chB));
            }
#pragma unroll
            for (int mt = 0; mt < 4; mt++)
#pragma unroll
                for (int nt = 0; nt < 8; nt++)
                    mma_tf32(acc[mt][nt], a[mt], bq[2 * nt], bq[2 * nt + 1]);
        }
    }
}

__device__ __forceinline__ void conv_epi64(
    float acc[4][8][4], int fBase64, int lBase64, int lane,
    const float* __restrict__ bias, float* __restrict__ out, int L, int b) {
    const int r4 = lane & 3, q = lane >> 2;
#pragma unroll
    for (int mt = 0; mt < 4; mt++) {
        int f0 = fBase64 + mt * 16 + q;
        float bv0 = (f0 < Fn) ? bias[f0] : 0.0f;
        float bv1 = (f0 + 8 < Fn) ? bias[f0 + 8] : 0.0f;
#pragma unroll
        for (int nt = 0; nt < 8; nt++) {
            int l = lBase64 + nt * 8 + r4 * 2;
            if (f0 < Fn) {
                float2 v = make_float2(acc[mt][nt][0] + bv0, acc[mt][nt][1] + bv0);
                *(float2*)(out + ((size_t)b * Fn + f0) * L + l) = v;
            }
            if (f0 + 8 < Fn) {
                float2 v = make_float2(acc[mt][nt][2] + bv1, acc[mt][nt][3] + bv1);
                *(float2*)(out + ((size_t)b * Fn + f0 + 8) * L + l) = v;
            }
        }
    }
}

// ---------------- merged conv kernel ----------------
// grid (3, 4, 512): blockIdx.x 0,1 -> A-conv (128f x 256l tile at lBase=x*256);
//                   blockIdx.x 2   -> fused Q+tQ conv (128f x 128l, dual weights).
__global__ void __launch_bounds__(256, 1)
conv_all(const int* __restrict__ question, const int* __restrict__ answer,
         const float* __restrict__ e32,
         const float* __restrict__ W1, const float* __restrict__ W2,
         const float* __restrict__ bias1, const float* __restrict__ bias2,
         float* __restrict__ Ao, float* __restrict__ Qo, float* __restrict__ tQo) {
    extern __shared__ uint32_t dsm[];
    __shared__ int stok[260];

    const int tid = threadIdx.x;
    const int wid = tid >> 5, lane = tid & 31;
    const int fBase = blockIdx.y * 128;
    const int b = blockIdx.z;
    const uint32_t sbase = smem_u32(dsm);

    float acc[4][8][4];
#pragma unroll
    for (int mt = 0; mt < 4; mt++)
#pragma unroll
        for (int nt = 0; nt < 8; nt++)
#pragma unroll
            for (int i = 0; i < 4; i++) acc[mt][nt][i] = 0.0f;

    if (blockIdx.x < 2) {
        // ---- A-conv path ----
        const int wm = wid & 1, wn = wid >> 1;       // 2f x 4l of 64x64
        const int lBase = blockIdx.x * 256;
        const bool fvalid = (fBase + wm * 64) < Fn;

        for (int i = tid; i < 260; i += 256) {
            int pos = lBase + i - 1;
            stok[i] = (pos >= 0 && pos < ALn && i < 258) ? answer[b * ALn + pos] : -1;
        }
        __syncthreads();

#pragma unroll
        for (int p = 0; p < 2; p++) {
            uint32_t stg = sbase + (uint32_t)p * STAGE_A;
            fill_w(stg, 0u, p * 16, tid, fBase, W1);
            fill_x<260>(stg, 768u, p * 16, tid, e32, stok);
            asm volatile("cp.async.commit_group;" ::: "memory");
        }
        for (int s = 0; s < NS; s++) {
            asm volatile("cp.async.wait_group 1;" ::: "memory");
            __syncthreads();
            if (s + 2 < NS) {
                uint32_t stg2 = sbase + (uint32_t)((s + 2) % NBUF) * STAGE_A;
                fill_w(stg2, 0u, (s + 2) * 16, tid, fBase, W1);
                fill_x<260>(stg2, 768u, (s + 2) * 16, tid, e32, stok);
            }
            asm volatile("cp.async.commit_group;" ::: "memory");
            const uint32_t stg = sbase + (uint32_t)(s % NBUF) * STAGE_A;
            if (fvalid)
                conv_cs64(stg, lane, (uint32_t)(wm * 64), 768u + (uint32_t)(wn * 64), 260u, acc);
        }
        if (fvalid)
            conv_epi64(acc, fBase + wm * 64, lBase + wn * 64, lane, bias1, Ao, ALn, b);
    } else {
        // ---- fused Q + tQ path ----
        const int ws = wid >> 2;                      // weight set 0 (Q) / 1 (tQ)
        const int wm = wid & 1, wn = (wid >> 1) & 1;  // 2f x 2l of 64x64
        const bool fvalid = (fBase + wm * 64) < Fn;

        if (tid < 132) {
            int pos = tid - 1;
            stok[tid] = (pos >= 0 && pos < QLn && tid < 130) ? question[b * QLn + pos] : -1;
        }
        __syncthreads();

#pragma unroll
        for (int p = 0; p < 2; p++) {
            uint32_t stg = sbase + (uint32_t)p * STAGE_Q;
            fill_w(stg, 0u, p * 16, tid, fBase, W1);
            fill_w(stg, 768u, p * 16, tid, fBase, W2);
            fill_x<132>(stg, 1536u, p * 16, tid, e32, stok);
            asm volatile("cp.async.commit_group;" ::: "memory");
        }
        for (int s = 0; s < NS; s++) {
            asm volatile("cp.async.wait_group 1;" ::: "memory");
            __syncthreads();
            if (s + 2 < NS) {
                uint32_t stg2 = sbase + (uint32_t)((s + 2) % NBUF) * STAGE_Q;
                fill_w(stg2, 0u, (s + 2) * 16, tid, fBase, W1);
                fill_w(stg2, 768u, (s + 2) * 16, tid, fBase, W2);
                fill_x<132>(stg2, 1536u, (s + 2) * 16, tid, e32, stok);
            }
            asm volatile("cp.async.commit_group;" ::: "memory");
            const uint32_t stg = sbase + (uint32_t)(s % NBUF) * STAGE_Q;
            if (fvalid)
                conv_cs64(stg, lane, (uint32_t)(ws * 768 + wm * 64),
                          1536u + (uint32_t)(wn * 64), 132u, acc);
        }
        if (fvalid) {
            const float* bias = ws ? bias2 : bias1;
            float* out = ws ? tQo : Qo;
            conv_epi64(acc, fBase + wm * 64, wn * 64, lane, bias, out, QLn, b);
        }
    }
}

// ---------------- tf32 G-tile kernel ----------------
__global__ void __launch_bounds__(256)
g_mma(const float* __restrict__ tQ, const float* __restrict__ A,
      float* __restrict__ maxQp, float* __restrict__ maxA) {
    __shared__ __align__(16) uint32_t stg[4096];  // 16 KB
    __shared__ float sRow[2][128];
    __shared__ float sCol[4][128];

    const int tid = threadIdx.x;
    const int wid = tid >> 5, lane = tid & 31;
    const int wmf = wid & 3, wnf = wid >> 2;
    const int r4 = lane & 3, q8 = lane >> 2;
    const int at = blockIdx.x, b = blockIdx.y;

    const float* tqb = tQ + (size_t)b * Fn * QLn;
    const float* ab  = A  + (size_t)b * Fn * ALn + at * 128;
    const int role = tid >> 7;
    const int rrow = tid & 127;
    const float* src = role ? (ab + rrow) : (tqb + rrow);
    const int sstr = role ? ALn : QLn;
    const uint32_t sb = smem_u32(stg);

    const uint32_t frA = (((uint32_t)lane >> 3) & 1u) * 8u + ((uint32_t)lane & 7u);
    const uint32_t chA = (uint32_t)lane >> 4;
    const uint32_t frB = (((uint32_t)lane >> 4) << 3) + ((uint32_t)lane & 7u);
    const uint32_t chB = ((uint32_t)lane >> 3) & 1u;

    float acc[2][8][4];
#pragma unroll
    for (int mt = 0; mt < 2; mt++)
#pragma unroll
        for (int nt = 0; nt < 8; nt++)
#pragma unroll
            for (int i = 0; i < 4; i++) acc[mt][nt][i] = 0.0f;

    float v[16];
#pragma unroll
    for (int i = 0; i < 16; i++) v[i] = src[(size_t)i * sstr];

    for (int s = 0; s < 25; s++) {
        uint32_t w[16];
#pragma unroll
        for (int i = 0; i < 16; i++) w[i] = tf32_bits(v[i]);
        uint32_t rowS = (uint32_t)(role * 256 + rrow);
        sts128(swaddr(sb, rowS, 0), w[0], w[1], w[2], w[3]);
        sts128(swaddr(sb, rowS, 1), w[4], w[5], w[6], w[7]);
        sts128(swaddr(sb, rowS + 128u, 0), w[8], w[9], w[10], w[11]);
        sts128(swaddr(sb, rowS + 128u, 1), w[12], w[13], w[14], w[15]);
        __syncthreads();
        if (s < 24) {
            const float* s2 = src + (size_t)(s + 1) * 16 * sstr;
#pragma unroll
            for (int i = 0; i < 16; i++) v[i] = s2[(size_t)i * sstr];
        }
#pragma unroll
        for (int sub = 0; sub < 2; sub++) {
            uint32_t a0[4], a1[4], bq[16];
            uint32_t rowA = (uint32_t)(sub * 128 + wmf * 32) + frA;
            ldsm4(a0, swaddr(sb, rowA, chA));
            ldsm4(a1, swaddr(sb, rowA + 16u, chA));
#pragma unroll
            for (int p = 0; p < 4; p++) {
                uint32_t rowB = 256u + (uint32_t)(sub * 128 + wnf * 64 + p * 16) + frB;
                ldsm4(bq + 4 * p, swaddr(sb, rowB, chB));
            }
#pragma unroll
            for (int nt = 0; nt < 8; nt++) {
                mma_tf32(acc[0][nt], a0, bq[2 * nt], bq[2 * nt + 1]);
                mma_tf32(acc[1][nt], a1, bq[2 * nt], bq[2 * nt + 1]);
            }
        }
        __syncthreads();
    }

#pragma unroll
    for (int mt = 0; mt < 2; mt++)
#pragma unroll
        for (int nt = 0; nt < 8; nt++)
#pragma unroll
            for (int ci = 0; ci < 4; ci++)
                acc[mt][nt][ci] = tanh_fast(acc[mt][nt][ci]);

    float rm[4] = {-2.f, -2.f, -2.f, -2.f};
    float cm[16];
#pragma unroll
    for (int i = 0; i < 16; i++) cm[i] = -2.f;
#pragma unroll
    for (int mt = 0; mt < 2; mt++)
#pragma unroll
        for (int nt = 0; nt < 8; nt++)
#pragma unroll
            for (int ci = 0; ci < 4; ci++) {
                float g = acc[mt][nt][ci];
                rm[mt * 2 + (ci >> 1)] = fmaxf(rm[mt * 2 + (ci >> 1)], g);
                cm[nt * 2 + (ci & 1)] = fmaxf(cm[nt * 2 + (ci & 1)], g);
            }
#pragma unroll
    for (int k = 0; k < 4; k++) {
        rm[k] = fmaxf(rm[k], __shfl_xor_sync(0xffffffffu, rm[k], 1));
        rm[k] = fmaxf(rm[k], __shfl_xor_sync(0xffffffffu, rm[k], 2));
    }
#pragma unroll
    for (int k = 0; k < 16; k++) {
        cm[k] = fmaxf(cm[k], __shfl_xor_sync(0xffffffffu, cm[k], 4));
        cm[k] = fmaxf(cm[k], __shfl_xor_sync(0xffffffffu, cm[k], 8));
        cm[k] = fmaxf(cm[k], __shfl_xor_sync(0xffffffffu, cm[k], 16));
    }
    if (r4 == 0) {
#pragma unroll
        for (int mt = 0; mt < 2; mt++)
#pragma unroll
            for (int h = 0; h < 2; h++)
                sRow[wnf][wmf * 32 + mt * 16 + h * 8 + q8] = rm[mt * 2 + h];
    }
    if (q8 == 0) {
#pragma unroll
        for (int nt = 0; nt < 8; nt++)
#pragma unroll
            for (int c = 0; c < 2; c++)
                sCol[wmf][wnf * 64 + nt * 8 + r4 * 2 + c] = cm[nt * 2 + c];
    }
    __syncthreads();
    if (tid < 128) {
        maxQp[((size_t)b * 4 + at) * QLn + tid] = fmaxf(sRow[0][tid], sRow[1][tid]);
        float m = fmaxf(fmaxf(sCol[0][tid], sCol[1][tid]), fmaxf(sCol[2][tid], sCol[3][tid]));
        maxA[(size_t)b * ALn + at * 128 + tid] = m;
    }
}

// ---------------- finalize ----------------
__device__ __forceinline__ float blkReduce(float v, bool domax) {
    __shared__ float sb[8];
#pragma unroll
    for (int o = 16; o; o >>= 1) {
        float ov = __shfl_xor_sync(0xffffffffu, v, o);
        v = domax ? fmaxf(v, ov) : v + ov;
    }
    __syncthreads();
    if ((threadIdx.x & 31) == 0) sb[threadIdx.x >> 5] = v;
    __syncthreads();
    float r = sb[0];
#pragma unroll
    for (int w = 1; w < 8; w++) r = domax ? fmaxf(r, sb[w]) : r + sb[w];
    return r;
}

__global__ void __launch_bounds__(256)
final_kernel(const float* __restrict__ Q, const float* __restrict__ A,
             const float* __restrict__ maxQp, const float* __restrict__ maxA,
             float* __restrict__ out) {
    __shared__ float roQ[QLn];
    __shared__ float roA[ALn];
    __shared__ float rQ[Fn];
    __shared__ float rA[Fn];
    const int b = blockIdx.x, tid = threadIdx.x;

    float v = -2.0f;
    if (tid < QLn) {
        const float* mp = maxQp + (size_t)b * 4 * QLn + tid;
        v = fmaxf(fmaxf(mp[0], mp[QLn]), fmaxf(mp[2 * QLn], mp[3 * QLn]));
    }
    float m = blkReduce(v, true);
    float e = (tid < QLn) ? __expf(v - m) : 0.0f;
    float s = blkReduce(e, false);
    if (tid < QLn) roQ[tid] = e / s;

    float v0 = maxA[(size_t)b * ALn + tid];
    float v1 = maxA[(size_t)b * ALn + 256 + tid];
    m = blkReduce(fmaxf(v0, v1), true);
    float e0 = __expf(v0 - m), e1 = __expf(v1 - m);
    s = blkReduce(e0 + e1, false);
    roA[tid] = e0 / s;
    roA[tid + 256] = e1 / s;
    __syncthreads();

    for (int f = tid; f < Fn; f += 256) {
        const float4* qr = (const float4*)(Q + ((size_t)b * Fn + f) * QLn);
        float a = 0.0f;
#pragma unroll 8
        for (int c = 0; c < QLn / 4; c++) {
            float4 qv = qr[c];
            const float* w = &roQ[c * 4];
            a += qv.x * w[0] + qv.y * w[1] + qv.z * w[2] + qv.w * w[3];
        }
        rQ[f] = a;
    }
    for (int f = tid; f < Fn; f += 256) {
        const float4* ar = (const float4*)(A + ((size_t)b * Fn + f) * ALn);
        float a = 0.0f;
#pragma unroll 8
        for (int c = 0; c < ALn / 4; c++) {
            float4 qv = ar[c];
            const float* w = &roA[c * 4];
            a += qv.x * w[0] + qv.y * w[1] + qv.z * w[2] + qv.w * w[3];
        }
        rA[f] = a;
    }
    __syncthreads();

    float d = 0.0f, qq = 0.0f, aa = 0.0f;
    for (int f = tid; f < Fn; f += 256) {
        float x = rQ[f], y = rA[f];
        d += x * y; qq += x * x; aa += y * y;
    }
    d = blkReduce(d, false);
    qq = blkReduce(qq, false);
    aa = blkReduce(aa, false);
    if (tid == 0)
        out[b] = d / (fmaxf(sqrtf(qq), 1e-8f) * fmaxf(sqrtf(aa), 1e-8f));
}

// ---------------- launch ----------------
extern "C" void kernel_launch(void* const* d_in, const int* in_sizes, int n_in,
                              void* d_out, int out_size) {
    const int*   question = (const int*)d_in[0];
    const int*   answer   = (const int*)d_in[1];
    const float* emb      = (const float*)d_in[2];
    const float* conv_w   = (const float*)d_in[3];
    const float* conv_b   = (const float*)d_in[4];
    const float* U        = (const float*)d_in[5];
    float* out = (float*)d_out;

    float *biasPad, *b2, *W32, *W232, *e32, *Ac, *Qc, *tQc, *maxQp, *maxA;
    cudaGetSymbolAddress((void**)&biasPad, d_biasPad);
    cudaGetSymbolAddress((void**)&b2,      d_b2);
    cudaGetSymbolAddress((void**)&W32,     d_W32);
    cudaGetSymbolAddress((void**)&W232,    d_W232);
    cudaGetSymbolAddress((void**)&e32,     d_emb32);
    cudaGetSymbolAddress((void**)&Ac,      d_A);
    cudaGetSymbolAddress((void**)&Qc,      d_Q);
    cudaGetSymbolAddress((void**)&tQc,     d_tQ);
    cudaGetSymbolAddress((void**)&maxQp,   d_maxQp);
    cudaGetSymbolAddress((void**)&maxA,    d_maxA);

    cudaFuncSetAttribute(conv_all, cudaFuncAttributeMaxDynamicSharedMemorySize, SMEM_ALL);

    const int prepBlocks = (3 * Fp * EPW + 255) / 256;
    prep_w<<<prepBlocks, 256>>>(conv_w, conv_b, biasPad, W32);
    prep_w2<<<prepBlocks, 256>>>(U, conv_b, conv_w, b2, W232);
    emb_cvt<<<(NEMBP + 255) / 256, 256>>>(emb, e32);

    dim3 gC(3, Fp / 128, Bn);   // x: 0,1 = A-tiles; 2 = Q-dual
    conv_all<<<gC, 256, SMEM_ALL>>>(question, answer, e32, W32, W232,
                                    biasPad, b2, Ac, Qc, tQc);

    dim3 gG(4, Bn);
    g_mma<<<gG, 256>>>(tQc, Ac, maxQp, maxA);
    final_kernel<<<Bn, 256>>>(Qc, Ac, maxQp, maxA, out);
}

// round 14
// speedup vs baseline: 1.0575x; 1.0034x over previous
#include <cuda_runtime.h>
#include <cstdint>
#include <cstddef>

constexpr int Bn  = 512;
constexpr int QLn = 128;
constexpr int ALn = 512;
constexpr int Fn  = 400;
constexpr int Fp  = 512;
constexpr int EPW = 304;                 // e padded to 19*16 (emb row stride, floats)
constexpr int NS  = 19;
constexpr int NEMBP = 50001 * EPW;
constexpr int NBUF = 3;
constexpr int STAGE_A = (768 + 520) * 32;          // 41216 B
constexpr int STAGE_Q = (768 + 768 + 264) * 32;    // 57600 B
constexpr int SMEM_ALL = NBUF * STAGE_Q;           // 172800 (max of both paths)

// ---------------- device scratch ----------------
__device__ __align__(256) float d_biasPad[Fp];
__device__ __align__(256) float d_b2[Fp];
__device__ __align__(256) float d_W32[3 * Fp * EPW];    // tf32 conv_w [j][f][e]
__device__ __align__(256) float d_W232[3 * Fp * EPW];   // tf32 U^T conv_w
__device__ __align__(256) float d_emb32[NEMBP];         // tf32 padded emb
__device__ __align__(256) float d_A[(size_t)Bn * Fn * ALn];
__device__ __align__(256) float d_Q[(size_t)Bn * Fn * QLn];
__device__ __align__(256) float d_tQ[(size_t)Bn * Fn * QLn];
__device__ __align__(256) float d_maxQp[Bn * 4 * QLn];
__device__ __align__(256) float d_maxA[Bn * ALn];

// ---------------- helpers ----------------
__device__ __forceinline__ float tanh_fast(float x) {
    float e = __expf(2.0f * x);
    return 1.0f - __fdividef(2.0f, e + 1.0f);
}
__device__ __forceinline__ uint32_t smem_u32(const void* p) {
    uint32_t a;
    asm("{ .reg .u64 t; cvta.to.shared.u64 t, %1; cvt.u32.u64 %0, t; }" : "=r"(a) : "l"(p));
    return a;
}
__device__ __forceinline__ float to_tf32(float x) {
    uint32_t r;
    asm("cvt.rna.tf32.f32 %0, %1;" : "=r"(r) : "f"(x));
    return __uint_as_float(r);
}
__device__ __forceinline__ uint32_t tf32_bits(float x) {
    uint32_t r;
    asm("cvt.rna.tf32.f32 %0, %1;" : "=r"(r) : "f"(x));
    return r;
}
__device__ __forceinline__ void mma_tf32(float* c, const uint32_t* a, uint32_t b0, uint32_t b1) {
    asm volatile(
        "mma.sync.aligned.m16n8k8.row.col.f32.tf32.tf32.f32 "
        "{%0,%1,%2,%3}, {%4,%5,%6,%7}, {%8,%9}, {%0,%1,%2,%3};"
        : "+f"(c[0]), "+f"(c[1]), "+f"(c[2]), "+f"(c[3])
        : "r"(a[0]), "r"(a[1]), "r"(a[2]), "r"(a[3]), "r"(b0), "r"(b1));
}
__device__ __forceinline__ void ldsm4(uint32_t* r, uint32_t addr) {
    asm volatile("ldmatrix.sync.aligned.m8n8.x4.shared.b16 {%0,%1,%2,%3}, [%4];"
        : "=r"(r[0]), "=r"(r[1]), "=r"(r[2]), "=r"(r[3]) : "r"(addr));
}
__device__ __forceinline__ void cp16(uint32_t dst, const void* src, uint32_t sz) {
    asm volatile("cp.async.cg.shared.global [%0], [%1], 16, %2;"
        :: "r"(dst), "l"(src), "r"(sz) : "memory");
}
__device__ __forceinline__ void sts128(uint32_t addr, uint32_t w0, uint32_t w1,
                                       uint32_t w2, uint32_t w3) {
    asm volatile("st.shared.v4.b32 [%0], {%1,%2,%3,%4};"
        :: "r"(addr), "r"(w0), "r"(w1), "r"(w2), "r"(w3));
}
// row-major tiles of 32B rows (2x16B chunks), chunk XOR swizzle
__device__ __forceinline__ uint32_t swaddr(uint32_t base, uint32_t row, uint32_t chunk) {
    return base + row * 32u + ((chunk ^ ((row >> 2) & 1u)) << 4);
}

// ---------------- prep kernels ----------------
__global__ void prep_w(const float* __restrict__ cw, const float* __restrict__ cb,
                       float* __restrict__ biasPad, float* __restrict__ W32) {
    int idx = blockIdx.x * 256 + threadIdx.x;
    if (idx < Fp) biasPad[idx] = (idx < Fn) ? cb[idx] : 0.0f;
    if (idx >= 3 * Fp * EPW) return;
    int j = idx / (Fp * EPW), rem = idx - j * (Fp * EPW);
    int f = rem / EPW, e = rem - f * EPW;
    float v = 0.0f;
    if (f < Fn && e < 300) v = cw[(f * 300 + e) * 3 + j];
    W32[idx] = to_tf32(v);
}

__global__ void prep_w2(const float* __restrict__ U, const float* __restrict__ cb,
                        const float* __restrict__ cw, float* __restrict__ b2,
                        float* __restrict__ W232) {
    int idx = blockIdx.x * 256 + threadIdx.x;
    if (idx < Fp) {
        float a = 0.0f;
        if (idx < Fn) for (int f = 0; f < Fn; f++) a += U[f * Fn + idx] * cb[f];
        b2[idx] = a;
    }
    if (idx >= 3 * Fp * EPW) return;
    int j = idx / (Fp * EPW), rem = idx - j * (Fp * EPW);
    int g = rem / EPW, e = rem - g * EPW;
    float a = 0.0f;
    if (g < Fn && e < 300) {
#pragma unroll 4
        for (int f = 0; f < Fn; f++) a += U[f * Fn + g] * cw[(f * 300 + e) * 3 + j];
    }
    W232[idx] = to_tf32(a);
}

__global__ void emb_cvt(const float* __restrict__ emb, float* __restrict__ e32) {
    int idx = blockIdx.x * 256 + threadIdx.x;
    if (idx >= NEMBP) return;
    int t = idx / EPW, e = idx - t * EPW;
    float v = (e < 300) ? emb[(size_t)t * 300 + e] : 0.0f;
    e32[idx] = to_tf32(v);
}

// ---------------- fill pieces (256 threads), e-chunk = 16 ----------------
__device__ __forceinline__ void fill_w(
    uint32_t stage, uint32_t rowOff, int e0, int tid, int fBase,
    const float* __restrict__ W) {
#pragma unroll
    for (int it = 0; it < 6; it++) {
        int idx = it * 256 + tid;
        uint32_t row = (uint32_t)idx >> 1, chunk = idx & 1;
        uint32_t j2 = row >> 7, f = row & 127u;
        const float* src = W + ((size_t)(j2 >> 1) * Fp + fBase + f) * EPW
                         + e0 + (j2 & 1) * 8 + chunk * 4;
        cp16(swaddr(stage, rowOff + row, chunk), src, (fBase + (int)f < Fn) ? 16u : 0u);
    }
}

template <int NR>   // rows per sub-table
__device__ __forceinline__ void fill_x(
    uint32_t stage, uint32_t rowOff, int e0, int tid,
    const float* __restrict__ e32, const int* stok) {
    constexpr int NCH = NR * 4;   // 2 subchunks x 2 chunks x NR rows
#pragma unroll
    for (int it = 0; it < (NCH + 255) / 256; it++) {
        int idx = it * 256 + tid;
        if (idx < NCH) {
            uint32_t sub = (idx >= NR * 2) ? 1u : 0u;
            uint32_t rem = idx - sub * (NR * 2);
            uint32_t r = rem >> 1, chunk = rem & 1;
            int t = stok[r];
            const float* src = e32 + (size_t)(t < 0 ? 0 : t) * EPW
                             + e0 + sub * 8 + chunk * 4;
            cp16(swaddr(stage, rowOff + sub * (uint32_t)NR + r, chunk), src,
                 (t < 0) ? 0u : 16u);
        }
    }
}

// ---------------- 64x64-warp tf32 compute stage (e=16) ----------------
__device__ __forceinline__ void conv_cs64(
    uint32_t stg, int lane, uint32_t wRowBase, uint32_t xRowBase, uint32_t NRtab,
    float acc[4][8][4]) {
    const uint32_t frA = (((uint32_t)lane >> 3) & 1u) * 8u + ((uint32_t)lane & 7u);
    const uint32_t chA = (uint32_t)lane >> 4;
    const uint32_t frB = (((uint32_t)lane >> 4) << 3) + ((uint32_t)lane & 7u);
    const uint32_t chB = ((uint32_t)lane >> 3) & 1u;
#pragma unroll
    for (int j = 0; j < 3; j++) {
#pragma unroll
        for (int sub = 0; sub < 2; sub++) {
            uint32_t a[4][4], bq[16];
#pragma unroll
            for (int mt = 0; mt < 4; mt++) {
                uint32_t rowA = wRowBase + (uint32_t)(j * 256 + sub * 128 + mt * 16) + frA;
                ldsm4(a[mt], swaddr(stg, rowA, chA));
            }
#pragma unroll
            for (int p = 0; p < 4; p++) {
                uint32_t rowB = xRowBase + sub * NRtab + (uint32_t)(p * 16) + frB + (uint32_t)j;
                ldsm4(bq + 4 * p, swaddr(stg, rowB, chB));
            }
#pragma unroll
            for (int mt = 0; mt < 4; mt++)
#pragma unroll
                for (int nt = 0; nt < 8; nt++)
                    mma_tf32(acc[mt][nt], a[mt], bq[2 * nt], bq[2 * nt + 1]);
        }
    }
}

__device__ __forceinline__ void conv_epi64(
    float acc[4][8][4], int fBase64, int lBase64, int lane,
    const float* __restrict__ bias, float* __restrict__ out, int L, int b) {
    const int r4 = lane & 3, q = lane >> 2;
#pragma unroll
    for (int mt = 0; mt < 4; mt++) {
        int f0 = fBase64 + mt * 16 + q;
        float bv0 = (f0 < Fn) ? bias[f0] : 0.0f;
        float bv1 = (f0 + 8 < Fn) ? bias[f0 + 8] : 0.0f;
#pragma unroll
        for (int nt = 0; nt < 8; nt++) {
            int l = lBase64 + nt * 8 + r4 * 2;
            if (f0 < Fn) {
                float2 v = make_float2(acc[mt][nt][0] + bv0, acc[mt][nt][1] + bv0);
                *(float2*)(out + ((size_t)b * Fn + f0) * L + l) = v;
            }
            if (f0 + 8 < Fn) {
                float2 v = make_float2(acc[mt][nt][2] + bv1, acc[mt][nt][3] + bv1);
                *(float2*)(out + ((size_t)b * Fn + f0 + 8) * L + l) = v;
            }
        }
    }
}

// ---------------- merged conv kernel ----------------
// grid (3, 4, 512): blockIdx.x 0,1 -> A-conv (128f x 256l tile at lBase=x*256);
//                   blockIdx.x 2   -> fused Q+tQ conv (128f x 128l, dual weights).
__global__ void __launch_bounds__(256, 1)
conv_all(const int* __restrict__ question, const int* __restrict__ answer,
         const float* __restrict__ e32,
         const float* __restrict__ W1, const float* __restrict__ W2,
         const float* __restrict__ bias1, const float* __restrict__ bias2,
         float* __restrict__ Ao, float* __restrict__ Qo, float* __restrict__ tQo) {
    extern __shared__ uint32_t dsm[];
    __shared__ int stok[260];

    const int tid = threadIdx.x;
    const int wid = tid >> 5, lane = tid & 31;
    const int fBase = blockIdx.y * 128;
    const int b = blockIdx.z;
    const uint32_t sbase = smem_u32(dsm);

    float acc[4][8][4];
#pragma unroll
    for (int mt = 0; mt < 4; mt++)
#pragma unroll
        for (int nt = 0; nt < 8; nt++)
#pragma unroll
            for (int i = 0; i < 4; i++) acc[mt][nt][i] = 0.0f;

    if (blockIdx.x < 2) {
        // ---- A-conv path ----
        const int wm = wid & 1, wn = wid >> 1;       // 2f x 4l of 64x64
        const int lBase = blockIdx.x * 256;
        const bool fvalid = (fBase + wm * 64) < Fn;

        for (int i = tid; i < 260; i += 256) {
            int pos = lBase + i - 1;
            stok[i] = (pos >= 0 && pos < ALn && i < 258) ? answer[b * ALn + pos] : -1;
        }
        __syncthreads();

#pragma unroll
        for (int p = 0; p < 2; p++) {
            uint32_t stg = sbase + (uint32_t)p * STAGE_A;
            fill_w(stg, 0u, p * 16, tid, fBase, W1);
            fill_x<260>(stg, 768u, p * 16, tid, e32, stok);
            asm volatile("cp.async.commit_group;" ::: "memory");
        }
        for (int s = 0; s < NS; s++) {
            asm volatile("cp.async.wait_group 1;" ::: "memory");
            __syncthreads();
            if (s + 2 < NS) {
                uint32_t stg2 = sbase + (uint32_t)((s + 2) % NBUF) * STAGE_A;
                fill_w(stg2, 0u, (s + 2) * 16, tid, fBase, W1);
                fill_x<260>(stg2, 768u, (s + 2) * 16, tid, e32, stok);
            }
            asm volatile("cp.async.commit_group;" ::: "memory");
            const uint32_t stg = sbase + (uint32_t)(s % NBUF) * STAGE_A;
            if (fvalid)
                conv_cs64(stg, lane, (uint32_t)(wm * 64), 768u + (uint32_t)(wn * 64), 260u, acc);
        }
        if (fvalid)
            conv_epi64(acc, fBase + wm * 64, lBase + wn * 64, lane, bias1, Ao, ALn, b);
    } else {
        // ---- fused Q + tQ path ----
        const int ws = wid >> 2;                      // weight set 0 (Q) / 1 (tQ)
        const int wm = wid & 1, wn = (wid >> 1) & 1;  // 2f x 2l of 64x64
        const bool fvalid = (fBase + wm * 64) < Fn;

        if (tid < 132) {
            int pos = tid - 1;
            stok[tid] = (pos >= 0 && pos < QLn && tid < 130) ? question[b * QLn + pos] : -1;
        }
        __syncthreads();

#pragma unroll
        for (int p = 0; p < 2; p++) {
            uint32_t stg = sbase + (uint32_t)p * STAGE_Q;
            fill_w(stg, 0u, p * 16, tid, fBase, W1);
            fill_w(stg, 768u, p * 16, tid, fBase, W2);
            fill_x<132>(stg, 1536u, p * 16, tid, e32, stok);
            asm volatile("cp.async.commit_group;" ::: "memory");
        }
        for (int s = 0; s < NS; s++) {
            asm volatile("cp.async.wait_group 1;" ::: "memory");
            __syncthreads();
            if (s + 2 < NS) {
                uint32_t stg2 = sbase + (uint32_t)((s + 2) % NBUF) * STAGE_Q;
                fill_w(stg2, 0u, (s + 2) * 16, tid, fBase, W1);
                fill_w(stg2, 768u, (s + 2) * 16, tid, fBase, W2);
                fill_x<132>(stg2, 1536u, (s + 2) * 16, tid, e32, stok);
            }
            asm volatile("cp.async.commit_group;" ::: "memory");
            const uint32_t stg = sbase + (uint32_t)(s % NBUF) * STAGE_Q;
            if (fvalid)
                conv_cs64(stg, lane, (uint32_t)(ws * 768 + wm * 64),
                          1536u + (uint32_t)(wn * 64), 132u, acc);
        }
        if (fvalid) {
            const float* bias = ws ? bias2 : bias1;
            float* out = ws ? tQo : Qo;
            conv_epi64(acc, fBase + wm * 64, wn * 64, lane, bias, out, QLn, b);
        }
    }
}

// ---------------- tf32 G-tile kernel ----------------
__global__ void __launch_bounds__(256)
g_mma(const float* __restrict__ tQ, const float* __restrict__ A,
      float* __restrict__ maxQp, float* __restrict__ maxA) {
    __shared__ __align__(16) uint32_t stg[4096];  // 16 KB
    __shared__ float sRow[2][128];
    __shared__ float sCol[4][128];

    const int tid = threadIdx.x;
    const int wid = tid >> 5, lane = tid & 31;
    const int wmf = wid & 3, wnf = wid >> 2;
    const int r4 = lane & 3, q8 = lane >> 2;
    const int at = blockIdx.x, b = blockIdx.y;

    const float* tqb = tQ + (size_t)b * Fn * QLn;
    const float* ab  = A  + (size_t)b * Fn * ALn + at * 128;
    const int role = tid >> 7;
    const int rrow = tid & 127;
    const float* src = role ? (ab + rrow) : (tqb + rrow);
    const int sstr = role ? ALn : QLn;
    const uint32_t sb = smem_u32(stg);

    const uint32_t frA = (((uint32_t)lane >> 3) & 1u) * 8u + ((uint32_t)lane & 7u);
    const uint32_t chA = (uint32_t)lane >> 4;
    const uint32_t frB = (((uint32_t)lane >> 4) << 3) + ((uint32_t)lane & 7u);
    const uint32_t chB = ((uint32_t)lane >> 3) & 1u;

    float acc[2][8][4];
#pragma unroll
    for (int mt = 0; mt < 2; mt++)
#pragma unroll
        for (int nt = 0; nt < 8; nt++)
#pragma unroll
            for (int i = 0; i < 4; i++) acc[mt][nt][i] = 0.0f;

    float v[16];
#pragma unroll
    for (int i = 0; i < 16; i++) v[i] = src[(size_t)i * sstr];

    for (int s = 0; s < 25; s++) {
        uint32_t w[16];
#pragma unroll
        for (int i = 0; i < 16; i++) w[i] = tf32_bits(v[i]);
        uint32_t rowS = (uint32_t)(role * 256 + rrow);
        sts128(swaddr(sb, rowS, 0), w[0], w[1], w[2], w[3]);
        sts128(swaddr(sb, rowS, 1), w[4], w[5], w[6], w[7]);
        sts128(swaddr(sb, rowS + 128u, 0), w[8], w[9], w[10], w[11]);
        sts128(swaddr(sb, rowS + 128u, 1), w[12], w[13], w[14], w[15]);
        __syncthreads();
        if (s < 24) {
            const float* s2 = src + (size_t)(s + 1) * 16 * sstr;
#pragma unroll
            for (int i = 0; i < 16; i++) v[i] = s2[(size_t)i * sstr];
        }
#pragma unroll
        for (int sub = 0; sub < 2; sub++) {
            uint32_t a0[4], a1[4], bq[16];
            uint32_t rowA = (uint32_t)(sub * 128 + wmf * 32) + frA;
            ldsm4(a0, swaddr(sb, rowA, chA));
            ldsm4(a1, swaddr(sb, rowA + 16u, chA));
#pragma unroll
            for (int p = 0; p < 4; p++) {
                uint32_t rowB = 256u + (uint32_t)(sub * 128 + wnf * 64 + p * 16) + frB;
                ldsm4(bq + 4 * p, swaddr(sb, rowB, chB));
            }
#pragma unroll
            for (int nt = 0; nt < 8; nt++) {
                mma_tf32(acc[0][nt], a0, bq[2 * nt], bq[2 * nt + 1]);
                mma_tf32(acc[1][nt], a1, bq[2 * nt], bq[2 * nt + 1]);
            }
        }
        __syncthreads();
    }

#pragma unroll
    for (int mt = 0; mt < 2; mt++)
#pragma unroll
        for (int nt = 0; nt < 8; nt++)
#pragma unroll
            for (int ci = 0; ci < 4; ci++)
                acc[mt][nt][ci] = tanh_fast(acc[mt][nt][ci]);

    float rm[4] = {-2.f, -2.f, -2.f, -2.f};
    float cm[16];
#pragma unroll
    for (int i = 0; i < 16; i++) cm[i] = -2.f;
#pragma unroll
    for (int mt = 0; mt < 2; mt++)
#pragma unroll
        for (int nt = 0; nt < 8; nt++)
#pragma unroll
            for (int ci = 0; ci < 4; ci++) {
                float g = acc[mt][nt][ci];
                rm[mt * 2 + (ci >> 1)] = fmaxf(rm[mt * 2 + (ci >> 1)], g);
                cm[nt * 2 + (ci & 1)] = fmaxf(cm[nt * 2 + (ci & 1)], g);
            }
#pragma unroll
    for (int k = 0; k < 4; k++) {
        rm[k] = fmaxf(rm[k], __shfl_xor_sync(0xffffffffu, rm[k], 1));
        rm[k] = fmaxf(rm[k], __shfl_xor_sync(0xffffffffu, rm[k], 2));
    }
#pragma unroll
    for (int k = 0; k < 16; k++) {
        cm[k] = fmaxf(cm[k], __shfl_xor_sync(0xffffffffu, cm[k], 4));
        cm[k] = fmaxf(cm[k], __shfl_xor_sync(0xffffffffu, cm[k], 8));
        cm[k] = fmaxf(cm[k], __shfl_xor_sync(0xffffffffu, cm[k], 16));
    }
    if (r4 == 0) {
#pragma unroll
        for (int mt = 0; mt < 2; mt++)
#pragma unroll
            for (int h = 0; h < 2; h++)
                sRow[wnf][wmf * 32 + mt * 16 + h * 8 + q8] = rm[mt * 2 + h];
    }
    if (q8 == 0) {
#pragma unroll
        for (int nt = 0; nt < 8; nt++)
#pragma unroll
            for (int c = 0; c < 2; c++)
                sCol[wmf][wnf * 64 + nt * 8 + r4 * 2 + c] = cm[nt * 2 + c];
    }
    __syncthreads();
    if (tid < 128) {
        maxQp[((size_t)b * 4 + at) * QLn + tid] = fmaxf(sRow[0][tid], sRow[1][tid]);
        float m = fmaxf(fmaxf(sCol[0][tid], sCol[1][tid]), fmaxf(sCol[2][tid], sCol[3][tid]));
        maxA[(size_t)b * ALn + at * 128 + tid] = m;
    }
}

// ---------------- finalize ----------------
__device__ __forceinline__ float blkReduce(float v, bool domax) {
    __shared__ float sb[8];
#pragma unroll
    for (int o = 16; o; o >>= 1) {
        float ov = __shfl_xor_sync(0xffffffffu, v, o);
        v = domax ? fmaxf(v, ov) : v + ov;
    }
    __syncthreads();
    if ((threadIdx.x & 31) == 0) sb[threadIdx.x >> 5] = v;
    __syncthreads();
    float r = sb[0];
#pragma unroll
    for (int w = 1; w < 8; w++) r = domax ? fmaxf(r, sb[w]) : r + sb[w];
    return r;
}

__global__ void __launch_bounds__(256)
final_kernel(const float* __restrict__ Q, const float* __restrict__ A,
             const float* __restrict__ maxQp, const float* __restrict__ maxA,
             float* __restrict__ out) {
    __shared__ float roQ[QLn];
    __shared__ float roA[ALn];
    __shared__ float rQ[Fn];
    __shared__ float rA[Fn];
    const int b = blockIdx.x, tid = threadIdx.x;

    float v = -2.0f;
    if (tid < QLn) {
        const float* mp = maxQp + (size_t)b * 4 * QLn + tid;
        v = fmaxf(fmaxf(mp[0], mp[QLn]), fmaxf(mp[2 * QLn], mp[3 * QLn]));
    }
    float m = blkReduce(v, true);
    float e = (tid < QLn) ? __expf(v - m) : 0.0f;
    float s = blkReduce(e, false);
    if (tid < QLn) roQ[tid] = e / s;

    float v0 = maxA[(size_t)b * ALn + tid];
    float v1 = maxA[(size_t)b * ALn + 256 + tid];
    m = blkReduce(fmaxf(v0, v1), true);
    float e0 = __expf(v0 - m), e1 = __expf(v1 - m);
    s = blkReduce(e0 + e1, false);
    roA[tid] = e0 / s;
    roA[tid + 256] = e1 / s;
    __syncthreads();

    for (int f = tid; f < Fn; f += 256) {
        const float4* qr = (const float4*)(Q + ((size_t)b * Fn + f) * QLn);
        float a = 0.0f;
#pragma unroll 8
        for (int c = 0; c < QLn / 4; c++) {
            float4 qv = qr[c];
            const float* w = &roQ[c * 4];
            a += qv.x * w[0] + qv.y * w[1] + qv.z * w[2] + qv.w * w[3];
        }
        rQ[f] = a;
    }
    for (int f = tid; f < Fn; f += 256) {
        const float4* ar = (const float4*)(A + ((size_t)b * Fn + f) * ALn);
        float a = 0.0f;
#pragma unroll 8
        for (int c = 0; c < ALn / 4; c++) {
            float4 qv = ar[c];
            const float* w = &roA[c * 4];
            a += qv.x * w[0] + qv.y * w[1] + qv.z * w[2] + qv.w * w[3];
        }
        rA[f] = a;
    }
    __syncthreads();

    float d = 0.0f, qq = 0.0f, aa = 0.0f;
    for (int f = tid; f < Fn; f += 256) {
        float x = rQ[f], y = rA[f];
        d += x * y; qq += x * x; aa += y * y;
    }
    d = blkReduce(d, false);
    qq = blkReduce(qq, false);
    aa = blkReduce(aa, false);
    if (tid == 0)
        out[b] = d / (fmaxf(sqrtf(qq), 1e-8f) * fmaxf(sqrtf(aa), 1e-8f));
}

// ---------------- launch ----------------
extern "C" void kernel_launch(void* const* d_in, const int* in_sizes, int n_in,
                              void* d_out, int out_size) {
    const int*   question = (const int*)d_in[0];
    const int*   answer   = (const int*)d_in[1];
    const float* emb      = (const float*)d_in[2];
    const float* conv_w   = (const float*)d_in[3];
    const float* conv_b   = (const float*)d_in[4];
    const float* U        = (const float*)d_in[5];
    float* out = (float*)d_out;

    float *biasPad, *b2, *W32, *W232, *e32, *Ac, *Qc, *tQc, *maxQp, *maxA;
    cudaGetSymbolAddress((void**)&biasPad, d_biasPad);
    cudaGetSymbolAddress((void**)&b2,      d_b2);
    cudaGetSymbolAddress((void**)&W32,     d_W32);
    cudaGetSymbolAddress((void**)&W232,    d_W232);
    cudaGetSymbolAddress((void**)&e32,     d_emb32);
    cudaGetSymbolAddress((void**)&Ac,      d_A);
    cudaGetSymbolAddress((void**)&Qc,      d_Q);
    cudaGetSymbolAddress((void**)&tQc,     d_tQ);
    cudaGetSymbolAddress((void**)&maxQp,   d_maxQp);
    cudaGetSymbolAddress((void**)&maxA,    d_maxA);

    cudaFuncSetAttribute(conv_all, cudaFuncAttributeMaxDynamicSharedMemorySize, SMEM_ALL);

    const int prepBlocks = (3 * Fp * EPW + 255) / 256;
    prep_w<<<prepBlocks, 256>>>(conv_w, conv_b, biasPad, W32);
    prep_w2<<<prepBlocks, 256>>>(U, conv_b, conv_w, b2, W232);
    emb_cvt<<<(NEMBP + 255) / 256, 256>>>(emb, e32);

    dim3 gC(3, Fp / 128, Bn);   // x: 0,1 = A-tiles; 2 = Q-dual
    conv_all<<<gC, 256, SMEM_ALL>>>(question, answer, e32, W32, W232,
                                    biasPad, b2, Ac, Qc, tQc);

    dim3 gG(4, Bn);
    g_mma<<<gG, 256>>>(tQc, Ac, maxQp, maxA);
    final_kernel<<<Bn, 256>>>(Qc, Ac, maxQp, maxA, out);
}

// round 15
// speedup vs baseline: 1.7758x; 1.6793x over previous
#include <cuda_runtime.h>
#include <cuda_fp16.h>
#include <cstdint>
#include <cstddef>
#include <cstring>

constexpr int Bn  = 512;
constexpr int QLn = 128;
constexpr int ALn = 512;
constexpr int Fn  = 400;
constexpr int Fp  = 512;
constexpr int EPW = 304;                 // e padded to 19*16 (emb row stride, halves)
constexpr int NS  = 19;
constexpr int NEMBP = 50001 * EPW;
constexpr int NBUF = 3;
// fp16: rows of 32B = 16 halves = one k16 chunk
constexpr int STAGE_A = (384 + 260) * 32;          // 20608 B
constexpr int STAGE_Q = (768 + 132) * 32;          // 28800 B
constexpr int SMEM_ALL = NBUF * STAGE_Q;           // 86400

// ---------------- device scratch ----------------
__device__ __align__(256) float d_biasPad[Fp];
__device__ __align__(256) float d_b2[Fp];
__device__ __align__(256) __half d_W16[3 * Fp * EPW];    // fp16 conv_w [j][f][e]
__device__ __align__(256) __half d_W216[3 * Fp * EPW];   // fp16 U^T conv_w
__device__ __align__(256) __half d_emb16[NEMBP];         // fp16 padded emb
__device__ __align__(256) float d_A[(size_t)Bn * Fn * ALn];
__device__ __align__(256) float d_Q[(size_t)Bn * Fn * QLn];
__device__ __align__(256) float d_tQ[(size_t)Bn * Fn * QLn];
__device__ __align__(256) float d_maxQp[Bn * 4 * QLn];
__device__ __align__(256) float d_maxA[Bn * ALn];

// ---------------- helpers ----------------
__device__ __forceinline__ float tanh_fast(float x) {
    float e = __expf(2.0f * x);
    return 1.0f - __fdividef(2.0f, e + 1.0f);
}
__device__ __forceinline__ uint32_t smem_u32(const void* p) {
    uint32_t a;
    asm("{ .reg .u64 t; cvta.to.shared.u64 t, %1; cvt.u32.u64 %0, t; }" : "=r"(a) : "l"(p));
    return a;
}
__device__ __forceinline__ uint32_t packh2(float v0, float v1) {
    __half2 h = __floats2half2_rn(v0, v1);
    uint32_t w;
    memcpy(&w, &h, 4);
    return w;
}
__device__ __forceinline__ void mma_f16(float* c, const uint32_t* a, uint32_t b0, uint32_t b1) {
    asm volatile(
        "mma.sync.aligned.m16n8k16.row.col.f32.f16.f16.f32 "
        "{%0,%1,%2,%3}, {%4,%5,%6,%7}, {%8,%9}, {%0,%1,%2,%3};"
        : "+f"(c[0]), "+f"(c[1]), "+f"(c[2]), "+f"(c[3])
        : "r"(a[0]), "r"(a[1]), "r"(a[2]), "r"(a[3]), "r"(b0), "r"(b1));
}
__device__ __forceinline__ void ldsm4(uint32_t* r, uint32_t addr) {
    asm volatile("ldmatrix.sync.aligned.m8n8.x4.shared.b16 {%0,%1,%2,%3}, [%4];"
        : "=r"(r[0]), "=r"(r[1]), "=r"(r[2]), "=r"(r[3]) : "r"(addr));
}
__device__ __forceinline__ void cp16(uint32_t dst, const void* src, uint32_t sz) {
    asm volatile("cp.async.cg.shared.global [%0], [%1], 16, %2;"
        :: "r"(dst), "l"(src), "r"(sz) : "memory");
}
__device__ __forceinline__ void sts128(uint32_t addr, uint32_t w0, uint32_t w1,
                                       uint32_t w2, uint32_t w3) {
    asm volatile("st.shared.v4.b32 [%0], {%1,%2,%3,%4};"
        :: "r"(addr), "r"(w0), "r"(w1), "r"(w2), "r"(w3));
}
// row-major tiles of 32B rows (2x16B chunks), chunk XOR swizzle
__device__ __forceinline__ uint32_t swaddr(uint32_t base, uint32_t row, uint32_t chunk) {
    return base + row * 32u + ((chunk ^ ((row >> 2) & 1u)) << 4);
}

// ---------------- prep kernels ----------------
__global__ void prep_w(const float* __restrict__ cw, const float* __restrict__ cb,
                       float* __restrict__ biasPad, __half* __restrict__ W16) {
    int idx = blockIdx.x * 256 + threadIdx.x;
    if (idx < Fp) biasPad[idx] = (idx < Fn) ? cb[idx] : 0.0f;
    if (idx >= 3 * Fp * EPW) return;
    int j = idx / (Fp * EPW), rem = idx - j * (Fp * EPW);
    int f = rem / EPW, e = rem - f * EPW;
    float v = 0.0f;
    if (f < Fn && e < 300) v = cw[(f * 300 + e) * 3 + j];
    W16[idx] = __float2half_rn(v);
}

__global__ void prep_w2(const float* __restrict__ U, const float* __restrict__ cb,
                        const float* __restrict__ cw, float* __restrict__ b2,
                        __half* __restrict__ W216) {
    int idx = blockIdx.x * 256 + threadIdx.x;
    if (idx < Fp) {
        float a = 0.0f;
        if (idx < Fn) for (int f = 0; f < Fn; f++) a += U[f * Fn + idx] * cb[f];
        b2[idx] = a;
    }
    if (idx >= 3 * Fp * EPW) return;
    int j = idx / (Fp * EPW), rem = idx - j * (Fp * EPW);
    int g = rem / EPW, e = rem - g * EPW;
    float a = 0.0f;
    if (g < Fn && e < 300) {
#pragma unroll 4
        for (int f = 0; f < Fn; f++) a += U[f * Fn + g] * cw[(f * 300 + e) * 3 + j];
    }
    W216[idx] = __float2half_rn(a);
}

__global__ void emb_cvt(const float* __restrict__ emb, __half* __restrict__ e16) {
    int idx = blockIdx.x * 256 + threadIdx.x;
    if (idx >= NEMBP) return;
    int t = idx / EPW, e = idx - t * EPW;
    float v = (e < 300) ? emb[(size_t)t * 300 + e] : 0.0f;
    e16[idx] = __float2half_rn(v);
}

// ---------------- fill pieces (256 threads), k-chunk = 16 halves/row ----------------
// One weight set: rows [0,384): row = j*128 + f. 768 chunk-loads.
__device__ __forceinline__ void fill_w(
    uint32_t stage, uint32_t rowOff, int e0, int tid, int fBase,
    const __half* __restrict__ W) {
#pragma unroll
    for (int it = 0; it < 3; it++) {
        int idx = it * 256 + tid;
        uint32_t row = (uint32_t)idx >> 1, chunk = idx & 1;
        uint32_t j = row >> 7, f = row & 127u;
        const __half* src = W + ((size_t)j * Fp + fBase + f) * EPW + e0 + chunk * 8;
        cp16(swaddr(stage, rowOff + row, chunk), src, (fBase + (int)f < Fn) ? 16u : 0u);
    }
}

template <int NR>   // rows (incl pad)
__device__ __forceinline__ void fill_x(
    uint32_t stage, uint32_t rowOff, int e0, int tid,
    const __half* __restrict__ e16, const int* stok) {
    constexpr int NCH = NR * 2;
#pragma unroll
    for (int it = 0; it < (NCH + 255) / 256; it++) {
        int idx = it * 256 + tid;
        if (idx < NCH) {
            uint32_t r = (uint32_t)idx >> 1, chunk = idx & 1;
            int t = stok[r];
            const __half* src = e16 + (size_t)(t < 0 ? 0 : t) * EPW + e0 + chunk * 8;
            cp16(swaddr(stage, rowOff + r, chunk), src, (t < 0) ? 0u : 16u);
        }
    }
}

// ---------------- 64x64-warp fp16 compute stage (k=16) ----------------
// W rows: wRowBase + j*128 + f; X rows: xRowBase + l + j.
__device__ __forceinline__ void conv_cs64(
    uint32_t stg, int lane, uint32_t wRowBase, uint32_t xRowBase,
    float acc[4][8][4]) {
    const uint32_t frA = (((uint32_t)lane >> 3) & 1u) * 8u + ((uint32_t)lane & 7u);
    const uint32_t chA = (uint32_t)lane >> 4;
    const uint32_t frB = (((uint32_t)lane >> 4) << 3) + ((uint32_t)lane & 7u);
    const uint32_t chB = ((uint32_t)lane >> 3) & 1u;
#pragma unroll
    for (int j = 0; j < 3; j++) {
        uint32_t a[4][4], bq[16];
#pragma unroll
        for (int mt = 0; mt < 4; mt++) {
            uint32_t rowA = wRowBase + (uint32_t)(j * 128 + mt * 16) + frA;
            ldsm4(a[mt], swaddr(stg, rowA, chA));
        }
#pragma unroll
        for (int p = 0; p < 4; p++) {
            uint32_t rowB = xRowBase + (uint32_t)(p * 16) + frB + (uint32_t)j;
            ldsm4(bq + 4 * p, swaddr(stg, rowB, chB));
        }
#pragma unroll
        for (int mt = 0; mt < 4; mt++)
#pragma unroll
            for (int nt = 0; nt < 8; nt++)
                mma_f16(acc[mt][nt], a[mt], bq[2 * nt], bq[2 * nt + 1]);
    }
}

__device__ __forceinline__ void conv_epi64(
    float acc[4][8][4], int fBase64, int lBase64, int lane,
    const float* __restrict__ bias, float* __restrict__ out, int L, int b) {
    const int r4 = lane & 3, q = lane >> 2;
#pragma unroll
    for (int mt = 0; mt < 4; mt++) {
        int f0 = fBase64 + mt * 16 + q;
        float bv0 = (f0 < Fn) ? bias[f0] : 0.0f;
        float bv1 = (f0 + 8 < Fn) ? bias[f0 + 8] : 0.0f;
#pragma unroll
        for (int nt = 0; nt < 8; nt++) {
            int l = lBase64 + nt * 8 + r4 * 2;
            if (f0 < Fn) {
                float2 v = make_float2(acc[mt][nt][0] + bv0, acc[mt][nt][1] + bv0);
                *(float2*)(out + ((size_t)b * Fn + f0) * L + l) = v;
            }
            if (f0 + 8 < Fn) {
                float2 v = make_float2(acc[mt][nt][2] + bv1, acc[mt][nt][3] + bv1);
                *(float2*)(out + ((size_t)b * Fn + f0 + 8) * L + l) = v;
            }
        }
    }
}

// ---------------- merged conv kernel ----------------
// grid (3, 4, 512): x 0,1 -> A-conv (128f x 256l); x=2 -> fused Q+tQ (128f x 128l).
__global__ void __launch_bounds__(256, 1)
conv_all(const int* __restrict__ question, const int* __restrict__ answer,
         const __half* __restrict__ e16,
         const __half* __restrict__ W1, const __half* __restrict__ W2,
         const float* __restrict__ bias1, const float* __restrict__ bias2,
         float* __restrict__ Ao, float* __restrict__ Qo, float* __restrict__ tQo) {
    extern __shared__ uint32_t dsm[];
    __shared__ int stok[260];

    const int tid = threadIdx.x;
    const int wid = tid >> 5, lane = tid & 31;
    const int fBase = blockIdx.y * 128;
    const int b = blockIdx.z;
    const uint32_t sbase = smem_u32(dsm);

    float acc[4][8][4];
#pragma unroll
    for (int mt = 0; mt < 4; mt++)
#pragma unroll
        for (int nt = 0; nt < 8; nt++)
#pragma unroll
            for (int i = 0; i < 4; i++) acc[mt][nt][i] = 0.0f;

    if (blockIdx.x < 2) {
        // ---- A-conv path ----
        const int wm = wid & 1, wn = wid >> 1;       // 2f x 4l of 64x64
        const int lBase = blockIdx.x * 256;
        const bool fvalid = (fBase + wm * 64) < Fn;

        for (int i = tid; i < 260; i += 256) {
            int pos = lBase + i - 1;
            stok[i] = (pos >= 0 && pos < ALn && i < 258) ? answer[b * ALn + pos] : -1;
        }
        __syncthreads();

#pragma unroll
        for (int p = 0; p < 2; p++) {
            uint32_t stg = sbase + (uint32_t)p * STAGE_A;
            fill_w(stg, 0u, p * 16, tid, fBase, W1);
            fill_x<260>(stg, 384u, p * 16, tid, e16, stok);
            asm volatile("cp.async.commit_group;" ::: "memory");
        }
        for (int s = 0; s < NS; s++) {
            asm volatile("cp.async.wait_group 1;" ::: "memory");
            __syncthreads();
            if (s + 2 < NS) {
                uint32_t stg2 = sbase + (uint32_t)((s + 2) % NBUF) * STAGE_A;
                fill_w(stg2, 0u, (s + 2) * 16, tid, fBase, W1);
                fill_x<260>(stg2, 384u, (s + 2) * 16, tid, e16, stok);
            }
            asm volatile("cp.async.commit_group;" ::: "memory");
            const uint32_t stg = sbase + (uint32_t)(s % NBUF) * STAGE_A;
            if (fvalid)
                conv_cs64(stg, lane, (uint32_t)(wm * 64), 384u + (uint32_t)(wn * 64), acc);
        }
        if (fvalid)
            conv_epi64(acc, fBase + wm * 64, lBase + wn * 64, lane, bias1, Ao, ALn, b);
    } else {
        // ---- fused Q + tQ path ----
        const int ws = wid >> 2;                      // weight set 0 (Q) / 1 (tQ)
        const int wm = wid & 1, wn = (wid >> 1) & 1;  // 2f x 2l of 64x64
        const bool fvalid = (fBase + wm * 64) < Fn;

        if (tid < 132) {
            int pos = tid - 1;
            stok[tid] = (pos >= 0 && pos < QLn && tid < 130) ? question[b * QLn + pos] : -1;
        }
        __syncthreads();

#pragma unroll
        for (int p = 0; p < 2; p++) {
            uint32_t stg = sbase + (uint32_t)p * STAGE_Q;
            fill_w(stg, 0u, p * 16, tid, fBase, W1);
            fill_w(stg, 384u, p * 16, tid, fBase, W2);
            fill_x<132>(stg, 768u, p * 16, tid, e16, stok);
            asm volatile("cp.async.commit_group;" ::: "memory");
        }
        for (int s = 0; s < NS; s++) {
            asm volatile("cp.async.wait_group 1;" ::: "memory");
            __syncthreads();
            if (s + 2 < NS) {
                uint32_t stg2 = sbase + (uint32_t)((s + 2) % NBUF) * STAGE_Q;
                fill_w(stg2, 0u, (s + 2) * 16, tid, fBase, W1);
                fill_w(stg2, 384u, (s + 2) * 16, tid, fBase, W2);
                fill_x<132>(stg2, 768u, (s + 2) * 16, tid, e16, stok);
            }
            asm volatile("cp.async.commit_group;" ::: "memory");
            const uint32_t stg = sbase + (uint32_t)(s % NBUF) * STAGE_Q;
            if (fvalid)
                conv_cs64(stg, lane, (uint32_t)(ws * 384 + wm * 64),
                          768u + (uint32_t)(wn * 64), acc);
        }
        if (fvalid) {
            const float* bias = ws ? bias2 : bias1;
            float* out = ws ? tQo : Qo;
            conv_epi64(acc, fBase + wm * 64, wn * 64, lane, bias, out, QLn, b);
        }
    }
}

// ---------------- fp16 G-tile kernel ----------------
// smem rows: tQ 0-127, A 128-255, 32B rows (16 halves = k16). stage 8 KB.
__global__ void __launch_bounds__(256)
g_mma(const float* __restrict__ tQ, const float* __restrict__ A,
      float* __restrict__ maxQp, float* __restrict__ maxA) {
    __shared__ __align__(16) uint32_t stg[2048];  // 8 KB
    __shared__ float sRow[2][128];
    __shared__ float sCol[4][128];

    const int tid = threadIdx.x;
    const int wid = tid >> 5, lane = tid & 31;
    const int wmf = wid & 3, wnf = wid >> 2;
    const int r4 = lane & 3, q8 = lane >> 2;
    const int at = blockIdx.x, b = blockIdx.y;

    const float* tqb = tQ + (size_t)b * Fn * QLn;
    const float* ab  = A  + (size_t)b * Fn * ALn + at * 128;
    const int role = tid >> 7;
    const int rrow = tid & 127;
    const float* src = role ? (ab + rrow) : (tqb + rrow);
    const int sstr = role ? ALn : QLn;
    const uint32_t sb = smem_u32(stg);

    const uint32_t frA = (((uint32_t)lane >> 3) & 1u) * 8u + ((uint32_t)lane & 7u);
    const uint32_t chA = (uint32_t)lane >> 4;
    const uint32_t frB = (((uint32_t)lane >> 4) << 3) + ((uint32_t)lane & 7u);
    const uint32_t chB = ((uint32_t)lane >> 3) & 1u;

    float acc[2][8][4];
#pragma unroll
    for (int mt = 0; mt < 2; mt++)
#pragma unroll
        for (int nt = 0; nt < 8; nt++)
#pragma unroll
            for (int i = 0; i < 4; i++) acc[mt][nt][i] = 0.0f;

    float v[16];
#pragma unroll
    for (int i = 0; i < 16; i++) v[i] = src[(size_t)i * sstr];

    for (int s = 0; s < 25; s++) {
        uint32_t w[8];
#pragma unroll
        for (int c = 0; c < 8; c++) w[c] = packh2(v[2 * c], v[2 * c + 1]);
        uint32_t rowS = (uint32_t)(role * 128 + rrow);
        sts128(swaddr(sb, rowS, 0), w[0], w[1], w[2], w[3]);
        sts128(swaddr(sb, rowS, 1), w[4], w[5], w[6], w[7]);
        __syncthreads();
        if (s < 24) {
            const float* s2 = src + (size_t)(s + 1) * 16 * sstr;
#pragma unroll
            for (int i = 0; i < 16; i++) v[i] = s2[(size_t)i * sstr];
        }
        uint32_t a[2][4], bq[16];
#pragma unroll
        for (int mt = 0; mt < 2; mt++) {
            uint32_t rowA = (uint32_t)(wmf * 32 + mt * 16) + frA;
            ldsm4(a[mt], swaddr(sb, rowA, chA));
        }
#pragma unroll
        for (int p = 0; p < 4; p++) {
            uint32_t rowB = 128u + (uint32_t)(wnf * 64 + p * 16) + frB;
            ldsm4(bq + 4 * p, swaddr(sb, rowB, chB));
        }
#pragma unroll
        for (int nt = 0; nt < 8; nt++) {
            mma_f16(acc[0][nt], a[0], bq[2 * nt], bq[2 * nt + 1]);
            mma_f16(acc[1][nt], a[1], bq[2 * nt], bq[2 * nt + 1]);
        }
        __syncthreads();
    }

#pragma unroll
    for (int mt = 0; mt < 2; mt++)
#pragma unroll
        for (int nt = 0; nt < 8; nt++)
#pragma unroll
            for (int ci = 0; ci < 4; ci++)
                acc[mt][nt][ci] = tanh_fast(acc[mt][nt][ci]);

    float rm[4] = {-2.f, -2.f, -2.f, -2.f};
    float cm[16];
#pragma unroll
    for (int i = 0; i < 16; i++) cm[i] = -2.f;
#pragma unroll
    for (int mt = 0; mt < 2; mt++)
#pragma unroll
        for (int nt = 0; nt < 8; nt++)
#pragma unroll
            for (int ci = 0; ci < 4; ci++) {
                float g = acc[mt][nt][ci];
                rm[mt * 2 + (ci >> 1)] = fmaxf(rm[mt * 2 + (ci >> 1)], g);
                cm[nt * 2 + (ci & 1)] = fmaxf(cm[nt * 2 + (ci & 1)], g);
            }
#pragma unroll
    for (int k = 0; k < 4; k++) {
        rm[k] = fmaxf(rm[k], __shfl_xor_sync(0xffffffffu, rm[k], 1));
        rm[k] = fmaxf(rm[k], __shfl_xor_sync(0xffffffffu, rm[k], 2));
    }
#pragma unroll
    for (int k = 0; k < 16; k++) {
        cm[k] = fmaxf(cm[k], __shfl_xor_sync(0xffffffffu, cm[k], 4));
        cm[k] = fmaxf(cm[k], __shfl_xor_sync(0xffffffffu, cm[k], 8));
        cm[k] = fmaxf(cm[k], __shfl_xor_sync(0xffffffffu, cm[k], 16));
    }
    if (r4 == 0) {
#pragma unroll
        for (int mt = 0; mt < 2; mt++)
#pragma unroll
            for (int h = 0; h < 2; h++)
                sRow[wnf][wmf * 32 + mt * 16 + h * 8 + q8] = rm[mt * 2 + h];
    }
    if (q8 == 0) {
#pragma unroll
        for (int nt = 0; nt < 8; nt++)
#pragma unroll
            for (int c = 0; c < 2; c++)
                sCol[wmf][wnf * 64 + nt * 8 + r4 * 2 + c] = cm[nt * 2 + c];
    }
    __syncthreads();
    if (tid < 128) {
        maxQp[((size_t)b * 4 + at) * QLn + tid] = fmaxf(sRow[0][tid], sRow[1][tid]);
        float m = fmaxf(fmaxf(sCol[0][tid], sCol[1][tid]), fmaxf(sCol[2][tid], sCol[3][tid]));
        maxA[(size_t)b * ALn + at * 128 + tid] = m;
    }
}

// ---------------- finalize ----------------
__device__ __forceinline__ float blkReduce(float v, bool domax) {
    __shared__ float sb[8];
#pragma unroll
    for (int o = 16; o; o >>= 1) {
        float ov = __shfl_xor_sync(0xffffffffu, v, o);
        v = domax ? fmaxf(v, ov) : v + ov;
    }
    __syncthreads();
    if ((threadIdx.x & 31) == 0) sb[threadIdx.x >> 5] = v;
    __syncthreads();
    float r = sb[0];
#pragma unroll
    for (int w = 1; w < 8; w++) r = domax ? fmaxf(r, sb[w]) : r + sb[w];
    return r;
}

__global__ void __launch_bounds__(256)
final_kernel(const float* __restrict__ Q, const float* __restrict__ A,
             const float* __restrict__ maxQp, const float* __restrict__ maxA,
             float* __restrict__ out) {
    __shared__ float roQ[QLn];
    __shared__ float roA[ALn];
    __shared__ float rQ[Fn];
    __shared__ float rA[Fn];
    const int b = blockIdx.x, tid = threadIdx.x;

    float v = -2.0f;
    if (tid < QLn) {
        const float* mp = maxQp + (size_t)b * 4 * QLn + tid;
        v = fmaxf(fmaxf(mp[0], mp[QLn]), fmaxf(mp[2 * QLn], mp[3 * QLn]));
    }
    float m = blkReduce(v, true);
    float e = (tid < QLn) ? __expf(v - m) : 0.0f;
    float s = blkReduce(e, false);
    if (tid < QLn) roQ[tid] = e / s;

    float v0 = maxA[(size_t)b * ALn + tid];
    float v1 = maxA[(size_t)b * ALn + 256 + tid];
    m = blkReduce(fmaxf(v0, v1), true);
    float e0 = __expf(v0 - m), e1 = __expf(v1 - m);
    s = blkReduce(e0 + e1, false);
    roA[tid] = e0 / s;
    roA[tid + 256] = e1 / s;
    __syncthreads();

    for (int f = tid; f < Fn; f += 256) {
        const float4* qr = (const float4*)(Q + ((size_t)b * Fn + f) * QLn);
        float a = 0.0f;
#pragma unroll 8
        for (int c = 0; c < QLn / 4; c++) {
            float4 qv = qr[c];
            const float* w = &roQ[c * 4];
            a += qv.x * w[0] + qv.y * w[1] + qv.z * w[2] + qv.w * w[3];
        }
        rQ[f] = a;
    }
    for (int f = tid; f < Fn; f += 256) {
        const float4* ar = (const float4*)(A + ((size_t)b * Fn + f) * ALn);
        float a = 0.0f;
#pragma unroll 8
        for (int c = 0; c < ALn / 4; c++) {
            float4 qv = ar[c];
            const float* w = &roA[c * 4];
            a += qv.x * w[0] + qv.y * w[1] + qv.z * w[2] + qv.w * w[3];
        }
        rA[f] = a;
    }
    __syncthreads();

    float d = 0.0f, qq = 0.0f, aa = 0.0f;
    for (int f = tid; f < Fn; f += 256) {
        float x = rQ[f], y = rA[f];
        d += x * y; qq += x * x; aa += y * y;
    }
    d = blkReduce(d, false);
    qq = blkReduce(qq, false);
    aa = blkReduce(aa, false);
    if (tid == 0)
        out[b] = d / (fmaxf(sqrtf(qq), 1e-8f) * fmaxf(sqrtf(aa), 1e-8f));
}

// ---------------- launch ----------------
extern "C" void kernel_launch(void* const* d_in, const int* in_sizes, int n_in,
                              void* d_out, int out_size) {
    const int*   question = (const int*)d_in[0];
    const int*   answer   = (const int*)d_in[1];
    const float* emb      = (const float*)d_in[2];
    const float* conv_w   = (const float*)d_in[3];
    const float* conv_b   = (const float*)d_in[4];
    const float* U        = (const float*)d_in[5];
    float* out = (float*)d_out;

    float *biasPad, *b2, *Ac, *Qc, *tQc, *maxQp, *maxA;
    __half *W16, *W216, *e16;
    cudaGetSymbolAddress((void**)&biasPad, d_biasPad);
    cudaGetSymbolAddress((void**)&b2,      d_b2);
    cudaGetSymbolAddress((void**)&W16,     d_W16);
    cudaGetSymbolAddress((void**)&W216,    d_W216);
    cudaGetSymbolAddress((void**)&e16,     d_emb16);
    cudaGetSymbolAddress((void**)&Ac,      d_A);
    cudaGetSymbolAddress((void**)&Qc,      d_Q);
    cudaGetSymbolAddress((void**)&tQc,     d_tQ);
    cudaGetSymbolAddress((void**)&maxQp,   d_maxQp);
    cudaGetSymbolAddress((void**)&maxA,    d_maxA);

    cudaFuncSetAttribute(conv_all, cudaFuncAttributeMaxDynamicSharedMemorySize, SMEM_ALL);

    const int prepBlocks = (3 * Fp * EPW + 255) / 256;
    prep_w<<<prepBlocks, 256>>>(conv_w, conv_b, biasPad, W16);
    prep_w2<<<prepBlocks, 256>>>(U, conv_b, conv_w, b2, W216);
    emb_cvt<<<(NEMBP + 255) / 256, 256>>>(emb, e16);

    dim3 gC(3, Fp / 128, Bn);   // x: 0,1 = A-tiles; 2 = Q-dual
    conv_all<<<gC, 256, SMEM_ALL>>>(question, answer, e16, W16, W216,
                                    biasPad, b2, Ac, Qc, tQc);

    dim3 gG(4, Bn);
    g_mma<<<gG, 256>>>(tQc, Ac, maxQp, maxA);
    final_kernel<<<Bn, 256>>>(Qc, Ac, maxQp, maxA, out);
}

// round 16
// speedup vs baseline: 1.8828x; 1.0603x over previous
#include <cuda_runtime.h>
#include <cuda_fp16.h>
#include <cstdint>
#include <cstddef>
#include <cstring>

constexpr int Bn  = 512;
constexpr int QLn = 128;
constexpr int ALn = 512;
constexpr int Fn  = 400;
constexpr int Fp  = 512;
constexpr int EPW = 304;                 // e padded to 19*16 (emb row stride, halves)
constexpr int NS  = 19;
constexpr int NEMBP = 50001 * EPW;
constexpr int NBUF = 3;
constexpr int STAGE = (384 + 132) * 32;  // 16512 B (W 384 rows + X 132 rows)
constexpr int SMEM_ALL = NBUF * STAGE;   // 49536

// ---------------- device scratch ----------------
__device__ __align__(256) float d_biasPad[Fp];
__device__ __align__(256) float d_b2[Fp];
__device__ __align__(256) __half d_W16[3 * Fp * EPW];    // fp16 conv_w [j][f][e]
__device__ __align__(256) __half d_W216[3 * Fp * EPW];   // fp16 U^T conv_w
__device__ __align__(256) __half d_emb16[NEMBP];         // fp16 padded emb
__device__ __align__(256) float d_A[(size_t)Bn * Fn * ALn];
__device__ __align__(256) float d_Q[(size_t)Bn * Fn * QLn];
__device__ __align__(256) float d_tQ[(size_t)Bn * Fn * QLn];
__device__ __align__(256) float d_maxQp[Bn * 4 * QLn];
__device__ __align__(256) float d_maxA[Bn * ALn];

// ---------------- helpers ----------------
__device__ __forceinline__ float tanh_fast(float x) {
    float e = __expf(2.0f * x);
    return 1.0f - __fdividef(2.0f, e + 1.0f);
}
__device__ __forceinline__ uint32_t smem_u32(const void* p) {
    uint32_t a;
    asm("{ .reg .u64 t; cvta.to.shared.u64 t, %1; cvt.u32.u64 %0, t; }" : "=r"(a) : "l"(p));
    return a;
}
__device__ __forceinline__ uint32_t packh2(float v0, float v1) {
    __half2 h = __floats2half2_rn(v0, v1);
    uint32_t w;
    memcpy(&w, &h, 4);
    return w;
}
__device__ __forceinline__ void mma_f16(float* c, const uint32_t* a, uint32_t b0, uint32_t b1) {
    asm volatile(
        "mma.sync.aligned.m16n8k16.row.col.f32.f16.f16.f32 "
        "{%0,%1,%2,%3}, {%4,%5,%6,%7}, {%8,%9}, {%0,%1,%2,%3};"
        : "+f"(c[0]), "+f"(c[1]), "+f"(c[2]), "+f"(c[3])
        : "r"(a[0]), "r"(a[1]), "r"(a[2]), "r"(a[3]), "r"(b0), "r"(b1));
}
__device__ __forceinline__ void ldsm4(uint32_t* r, uint32_t addr) {
    asm volatile("ldmatrix.sync.aligned.m8n8.x4.shared.b16 {%0,%1,%2,%3}, [%4];"
        : "=r"(r[0]), "=r"(r[1]), "=r"(r[2]), "=r"(r[3]) : "r"(addr));
}
__device__ __forceinline__ void cp16(uint32_t dst, const void* src, uint32_t sz) {
    asm volatile("cp.async.cg.shared.global [%0], [%1], 16, %2;"
        :: "r"(dst), "l"(src), "r"(sz) : "memory");
}
__device__ __forceinline__ void sts128(uint32_t addr, uint32_t w0, uint32_t w1,
                                       uint32_t w2, uint32_t w3) {
    asm volatile("st.shared.v4.b32 [%0], {%1,%2,%3,%4};"
        :: "r"(addr), "r"(w0), "r"(w1), "r"(w2), "r"(w3));
}
// row-major tiles of 32B rows (2x16B chunks), chunk XOR swizzle
__device__ __forceinline__ uint32_t swaddr(uint32_t base, uint32_t row, uint32_t chunk) {
    return base + row * 32u + ((chunk ^ ((row >> 2) & 1u)) << 4);
}

// ---------------- prep kernels ----------------
__global__ void prep_w(const float* __restrict__ cw, const float* __restrict__ cb,
                       float* __restrict__ biasPad, __half* __restrict__ W16) {
    int idx = blockIdx.x * 256 + threadIdx.x;
    if (idx < Fp) biasPad[idx] = (idx < Fn) ? cb[idx] : 0.0f;
    if (idx >= 3 * Fp * EPW) return;
    int j = idx / (Fp * EPW), rem = idx - j * (Fp * EPW);
    int f = rem / EPW, e = rem - f * EPW;
    float v = 0.0f;
    if (f < Fn && e < 300) v = cw[(f * 300 + e) * 3 + j];
    W16[idx] = __float2half_rn(v);
}

__global__ void prep_w2(const float* __restrict__ U, const float* __restrict__ cb,
                        const float* __restrict__ cw, float* __restrict__ b2,
                        __half* __restrict__ W216) {
    int idx = blockIdx.x * 256 + threadIdx.x;
    if (idx < Fp) {
        float a = 0.0f;
        if (idx < Fn) for (int f = 0; f < Fn; f++) a += U[f * Fn + idx] * cb[f];
        b2[idx] = a;
    }
    if (idx >= 3 * Fp * EPW) return;
    int j = idx / (Fp * EPW), rem = idx - j * (Fp * EPW);
    int g = rem / EPW, e = rem - g * EPW;
    float a = 0.0f;
    if (g < Fn && e < 300) {
#pragma unroll 4
        for (int f = 0; f < Fn; f++) a += U[f * Fn + g] * cw[(f * 300 + e) * 3 + j];
    }
    W216[idx] = __float2half_rn(a);
}

__global__ void emb_cvt(const float* __restrict__ emb, __half* __restrict__ e16) {
    int idx = blockIdx.x * 256 + threadIdx.x;
    if (idx >= NEMBP) return;
    int t = idx / EPW, e = idx - t * EPW;
    float v = (e < 300) ? emb[(size_t)t * 300 + e] : 0.0f;
    e16[idx] = __float2half_rn(v);
}

// ---------------- fill pieces (256 threads), k-chunk = 16 halves/row ----------------
// W rows [0,384): row = j*128 + f.
__device__ __forceinline__ void fill_w(
    uint32_t stage, int e0, int tid, int fBase, const __half* __restrict__ W) {
#pragma unroll
    for (int it = 0; it < 3; it++) {
        int idx = it * 256 + tid;
        uint32_t row = (uint32_t)idx >> 1, chunk = idx & 1;
        uint32_t j = row >> 7, f = row & 127u;
        const __half* src = W + ((size_t)j * Fp + fBase + f) * EPW + e0 + chunk * 8;
        cp16(swaddr(stage, row, chunk), src, (fBase + (int)f < Fn) ? 16u : 0u);
    }
}

// X rows [384, 384+132)
__device__ __forceinline__ void fill_x(
    uint32_t stage, int e0, int tid,
    const __half* __restrict__ e16, const int* stok) {
#pragma unroll
    for (int it = 0; it < 2; it++) {
        int idx = it * 256 + tid;
        if (idx < 264) {
            uint32_t r = (uint32_t)idx >> 1, chunk = idx & 1;
            int t = stok[r];
            const __half* src = e16 + (size_t)(t < 0 ? 0 : t) * EPW + e0 + chunk * 8;
            cp16(swaddr(stage, 384u + r, chunk), src, (t < 0) ? 0u : 16u);
        }
    }
}

// ---------------- 32f x 64l warp compute stage (k=48 per stage) ----------------
__device__ __forceinline__ void conv_cs32(
    uint32_t stg, int lane, uint32_t wRowBase, uint32_t xRowBase,
    float acc[2][8][4]) {
    const uint32_t frA = (((uint32_t)lane >> 3) & 1u) * 8u + ((uint32_t)lane & 7u);
    const uint32_t chA = (uint32_t)lane >> 4;
    const uint32_t frB = (((uint32_t)lane >> 4) << 3) + ((uint32_t)lane & 7u);
    const uint32_t chB = ((uint32_t)lane >> 3) & 1u;
#pragma unroll
    for (int j = 0; j < 3; j++) {
        uint32_t a[2][4], bq[16];
#pragma unroll
        for (int mt = 0; mt < 2; mt++) {
            uint32_t rowA = wRowBase + (uint32_t)(j * 128 + mt * 16) + frA;
            ldsm4(a[mt], swaddr(stg, rowA, chA));
        }
#pragma unroll
        for (int p = 0; p < 4; p++) {
            uint32_t rowB = xRowBase + (uint32_t)(p * 16) + frB + (uint32_t)j;
            ldsm4(bq + 4 * p, swaddr(stg, rowB, chB));
        }
#pragma unroll
        for (int mt = 0; mt < 2; mt++)
#pragma unroll
            for (int nt = 0; nt < 8; nt++)
                mma_f16(acc[mt][nt], a[mt], bq[2 * nt], bq[2 * nt + 1]);
    }
}

// ---------------- unified conv kernel ----------------
// grid (6, 4, 512): x<4 -> A-conv l-tile (lBase = x*128); x=4 -> Q; x=5 -> tQ.
// Tile 128f x 128l; 8 warps of 32f x 64l (wmf = wid&3, wnf = wid>>2).
__global__ void __launch_bounds__(256, 2)
conv_all(const int* __restrict__ question, const int* __restrict__ answer,
         const __half* __restrict__ e16,
         const __half* __restrict__ W1, const __half* __restrict__ W2,
         const float* __restrict__ bias1, const float* __restrict__ bias2,
         float* __restrict__ Ao, float* __restrict__ Qo, float* __restrict__ tQo) {
    extern __shared__ uint32_t dsm[];
    __shared__ int stok[132];

    const int tid = threadIdx.x;
    const int wid = tid >> 5, lane = tid & 31;
    const int wmf = wid & 3, wnf = wid >> 2;
    const int fBase = blockIdx.y * 128;
    const int b = blockIdx.z;
    const uint32_t sbase = smem_u32(dsm);
    const bool fvalid = (fBase + wmf * 32) < Fn;

    const int xi = blockIdx.x;
    const int* tok;
    int L, lBase;
    const __half* W;
    const float* bias;
    float* out;
    if (xi < 4) {
        tok = answer;  L = ALn;  lBase = xi * 128;
        W = W1;  bias = bias1;  out = Ao;
    } else if (xi == 4) {
        tok = question;  L = QLn;  lBase = 0;
        W = W1;  bias = bias1;  out = Qo;
    } else {
        tok = question;  L = QLn;  lBase = 0;
        W = W2;  bias = bias2;  out = tQo;
    }

    if (tid < 132) {
        int pos = lBase + tid - 1;
        stok[tid] = (pos >= 0 && pos < L && tid < 130) ? tok[b * L + pos] : -1;
    }
    __syncthreads();

    float acc[2][8][4];
#pragma unroll
    for (int mt = 0; mt < 2; mt++)
#pragma unroll
        for (int nt = 0; nt < 8; nt++)
#pragma unroll
            for (int i = 0; i < 4; i++) acc[mt][nt][i] = 0.0f;

#pragma unroll
    for (int p = 0; p < 2; p++) {
        uint32_t stg = sbase + (uint32_t)p * STAGE;
        fill_w(stg, p * 16, tid, fBase, W);
        fill_x(stg, p * 16, tid, e16, stok);
        asm volatile("cp.async.commit_group;" ::: "memory");
    }
    for (int s = 0; s < NS; s++) {
        asm volatile("cp.async.wait_group 1;" ::: "memory");
        __syncthreads();
        if (s + 2 < NS) {
            uint32_t stg2 = sbase + (uint32_t)((s + 2) % NBUF) * STAGE;
            fill_w(stg2, (s + 2) * 16, tid, fBase, W);
            fill_x(stg2, (s + 2) * 16, tid, e16, stok);
        }
        asm volatile("cp.async.commit_group;" ::: "memory");
        const uint32_t stg = sbase + (uint32_t)(s % NBUF) * STAGE;
        if (fvalid)
            conv_cs32(stg, lane, (uint32_t)(wmf * 32), 384u + (uint32_t)(wnf * 64), acc);
    }

    // epilogue (32f x 64l)
    if (fvalid) {
        const int r4 = lane & 3, q = lane >> 2;
#pragma unroll
        for (int mt = 0; mt < 2; mt++) {
            int f0 = fBase + wmf * 32 + mt * 16 + q;
            float bv0 = (f0 < Fn) ? bias[f0] : 0.0f;
            float bv1 = (f0 + 8 < Fn) ? bias[f0 + 8] : 0.0f;
#pragma unroll
            for (int nt = 0; nt < 8; nt++) {
                int l = lBase + wnf * 64 + nt * 8 + r4 * 2;
                if (f0 < Fn) {
                    float2 v = make_float2(acc[mt][nt][0] + bv0, acc[mt][nt][1] + bv0);
                    *(float2*)(out + ((size_t)b * Fn + f0) * L + l) = v;
                }
                if (f0 + 8 < Fn) {
                    float2 v = make_float2(acc[mt][nt][2] + bv1, acc[mt][nt][3] + bv1);
                    *(float2*)(out + ((size_t)b * Fn + f0 + 8) * L + l) = v;
                }
            }
        }
    }
}

// ---------------- fp16 G-tile kernel ----------------
__global__ void __launch_bounds__(256)
g_mma(const float* __restrict__ tQ, const float* __restrict__ A,
      float* __restrict__ maxQp, float* __restrict__ maxA) {
    __shared__ __align__(16) uint32_t stg[2048];  // 8 KB
    __shared__ float sRow[2][128];
    __shared__ float sCol[4][128];

    const int tid = threadIdx.x;
    const int wid = tid >> 5, lane = tid & 31;
    const int wmf = wid & 3, wnf = wid >> 2;
    const int r4 = lane & 3, q8 = lane >> 2;
    const int at = blockIdx.x, b = blockIdx.y;

    const float* tqb = tQ + (size_t)b * Fn * QLn;
    const float* ab  = A  + (size_t)b * Fn * ALn + at * 128;
    const int role = tid >> 7;
    const int rrow = tid & 127;
    const float* src = role ? (ab + rrow) : (tqb + rrow);
    const int sstr = role ? ALn : QLn;
    const uint32_t sb = smem_u32(stg);

    const uint32_t frA = (((uint32_t)lane >> 3) & 1u) * 8u + ((uint32_t)lane & 7u);
    const uint32_t chA = (uint32_t)lane >> 4;
    const uint32_t frB = (((uint32_t)lane >> 4) << 3) + ((uint32_t)lane & 7u);
    const uint32_t chB = ((uint32_t)lane >> 3) & 1u;

    float acc[2][8][4];
#pragma unroll
    for (int mt = 0; mt < 2; mt++)
#pragma unroll
        for (int nt = 0; nt < 8; nt++)
#pragma unroll
            for (int i = 0; i < 4; i++) acc[mt][nt][i] = 0.0f;

    float v[16];
#pragma unroll
    for (int i = 0; i < 16; i++) v[i] = src[(size_t)i * sstr];

    for (int s = 0; s < 25; s++) {
        uint32_t w[8];
#pragma unroll
        for (int c = 0; c < 8; c++) w[c] = packh2(v[2 * c], v[2 * c + 1]);
        uint32_t rowS = (uint32_t)(role * 128 + rrow);
        sts128(swaddr(sb, rowS, 0), w[0], w[1], w[2], w[3]);
        sts128(swaddr(sb, rowS, 1), w[4], w[5], w[6], w[7]);
        __syncthreads();
        if (s < 24) {
            const float* s2 = src + (size_t)(s + 1) * 16 * sstr;
#pragma unroll
            for (int i = 0; i < 16; i++) v[i] = s2[(size_t)i * sstr];
        }
        uint32_t a[2][4], bq[16];
#pragma unroll
        for (int mt = 0; mt < 2; mt++) {
            uint32_t rowA = (uint32_t)(wmf * 32 + mt * 16) + frA;
            ldsm4(a[mt], swaddr(sb, rowA, chA));
        }
#pragma unroll
        for (int p = 0; p < 4; p++) {
            uint32_t rowB = 128u + (uint32_t)(wnf * 64 + p * 16) + frB;
            ldsm4(bq + 4 * p, swaddr(sb, rowB, chB));
        }
#pragma unroll
        for (int nt = 0; nt < 8; nt++) {
            mma_f16(acc[0][nt], a[0], bq[2 * nt], bq[2 * nt + 1]);
            mma_f16(acc[1][nt], a[1], bq[2 * nt], bq[2 * nt + 1]);
        }
        __syncthreads();
    }

#pragma unroll
    for (int mt = 0; mt < 2; mt++)
#pragma unroll
        for (int nt = 0; nt < 8; nt++)
#pragma unroll
            for (int ci = 0; ci < 4; ci++)
                acc[mt][nt][ci] = tanh_fast(acc[mt][nt][ci]);

    float rm[4] = {-2.f, -2.f, -2.f, -2.f};
    float cm[16];
#pragma unroll
    for (int i = 0; i < 16; i++) cm[i] = -2.f;
#pragma unroll
    for (int mt = 0; mt < 2; mt++)
#pragma unroll
        for (int nt = 0; nt < 8; nt++)
#pragma unroll
            for (int ci = 0; ci < 4; ci++) {
                float g = acc[mt][nt][ci];
                rm[mt * 2 + (ci >> 1)] = fmaxf(rm[mt * 2 + (ci >> 1)], g);
                cm[nt * 2 + (ci & 1)] = fmaxf(cm[nt * 2 + (ci & 1)], g);
            }
#pragma unroll
    for (int k = 0; k < 4; k++) {
        rm[k] = fmaxf(rm[k], __shfl_xor_sync(0xffffffffu, rm[k], 1));
        rm[k] = fmaxf(rm[k], __shfl_xor_sync(0xffffffffu, rm[k], 2));
    }
#pragma unroll
    for (int k = 0; k < 16; k++) {
        cm[k] = fmaxf(cm[k], __shfl_xor_sync(0xffffffffu, cm[k], 4));
        cm[k] = fmaxf(cm[k], __shfl_xor_sync(0xffffffffu, cm[k], 8));
        cm[k] = fmaxf(cm[k], __shfl_xor_sync(0xffffffffu, cm[k], 16));
    }
    if (r4 == 0) {
#pragma unroll
        for (int mt = 0; mt < 2; mt++)
#pragma unroll
            for (int h = 0; h < 2; h++)
                sRow[wnf][wmf * 32 + mt * 16 + h * 8 + q8] = rm[mt * 2 + h];
    }
    if (q8 == 0) {
#pragma unroll
        for (int nt = 0; nt < 8; nt++)
#pragma unroll
            for (int c = 0; c < 2; c++)
                sCol[wmf][wnf * 64 + nt * 8 + r4 * 2 + c] = cm[nt * 2 + c];
    }
    __syncthreads();
    if (tid < 128) {
        maxQp[((size_t)b * 4 + at) * QLn + tid] = fmaxf(sRow[0][tid], sRow[1][tid]);
        float m = fmaxf(fmaxf(sCol[0][tid], sCol[1][tid]), fmaxf(sCol[2][tid], sCol[3][tid]));
        maxA[(size_t)b * ALn + at * 128 + tid] = m;
    }
}

// ---------------- finalize ----------------
__device__ __forceinline__ float blkReduce(float v, bool domax) {
    __shared__ float sb[8];
#pragma unroll
    for (int o = 16; o; o >>= 1) {
        float ov = __shfl_xor_sync(0xffffffffu, v, o);
        v = domax ? fmaxf(v, ov) : v + ov;
    }
    __syncthreads();
    if ((threadIdx.x & 31) == 0) sb[threadIdx.x >> 5] = v;
    __syncthreads();
    float r = sb[0];
#pragma unroll
    for (int w = 1; w < 8; w++) r = domax ? fmaxf(r, sb[w]) : r + sb[w];
    return r;
}

__global__ void __launch_bounds__(256)
final_kernel(const float* __restrict__ Q, const float* __restrict__ A,
             const float* __restrict__ maxQp, const float* __restrict__ maxA,
             float* __restrict__ out) {
    __shared__ float roQ[QLn];
    __shared__ float roA[ALn];
    __shared__ float rQ[Fn];
    __shared__ float rA[Fn];
    const int b = blockIdx.x, tid = threadIdx.x;

    float v = -2.0f;
    if (tid < QLn) {
        const float* mp = maxQp + (size_t)b * 4 * QLn + tid;
        v = fmaxf(fmaxf(mp[0], mp[QLn]), fmaxf(mp[2 * QLn], mp[3 * QLn]));
    }
    float m = blkReduce(v, true);
    float e = (tid < QLn) ? __expf(v - m) : 0.0f;
    float s = blkReduce(e, false);
    if (tid < QLn) roQ[tid] = e / s;

    float v0 = maxA[(size_t)b * ALn + tid];
    float v1 = maxA[(size_t)b * ALn + 256 + tid];
    m = blkReduce(fmaxf(v0, v1), true);
    float e0 = __expf(v0 - m), e1 = __expf(v1 - m);
    s = blkReduce(e0 + e1, false);
    roA[tid] = e0 / s;
    roA[tid + 256] = e1 / s;
    __syncthreads();

    for (int f = tid; f < Fn; f += 256) {
        const float4* qr = (const float4*)(Q + ((size_t)b * Fn + f) * QLn);
        float a = 0.0f;
#pragma unroll 8
        for (int c = 0; c < QLn / 4; c++) {
            float4 qv = qr[c];
            const float* w = &roQ[c * 4];
            a += qv.x * w[0] + qv.y * w[1] + qv.z * w[2] + qv.w * w[3];
        }
        rQ[f] = a;
    }
    for (int f = tid; f < Fn; f += 256) {
        const float4* ar = (const float4*)(A + ((size_t)b * Fn + f) * ALn);
        float a = 0.0f;
#pragma unroll 8
        for (int c = 0; c < ALn / 4; c++) {
            float4 qv = ar[c];
            const float* w = &roA[c * 4];
            a += qv.x * w[0] + qv.y * w[1] + qv.z * w[2] + qv.w * w[3];
        }
        rA[f] = a;
    }
    __syncthreads();

    float d = 0.0f, qq = 0.0f, aa = 0.0f;
    for (int f = tid; f < Fn; f += 256) {
        float x = rQ[f], y = rA[f];
        d += x * y; qq += x * x; aa += y * y;
    }
    d = blkReduce(d, false);
    qq = blkReduce(qq, false);
    aa = blkReduce(aa, false);
    if (tid == 0)
        out[b] = d / (fmaxf(sqrtf(qq), 1e-8f) * fmaxf(sqrtf(aa), 1e-8f));
}

// ---------------- launch ----------------
extern "C" void kernel_launch(void* const* d_in, const int* in_sizes, int n_in,
                              void* d_out, int out_size) {
    const int*   question = (const int*)d_in[0];
    const int*   answer   = (const int*)d_in[1];
    const float* emb      = (const float*)d_in[2];
    const float* conv_w   = (const float*)d_in[3];
    const float* conv_b   = (const float*)d_in[4];
    const float* U        = (const float*)d_in[5];
    float* out = (float*)d_out;

    float *biasPad, *b2, *Ac, *Qc, *tQc, *maxQp, *maxA;
    __half *W16, *W216, *e16;
    cudaGetSymbolAddress((void**)&biasPad, d_biasPad);
    cudaGetSymbolAddress((void**)&b2,      d_b2);
    cudaGetSymbolAddress((void**)&W16,     d_W16);
    cudaGetSymbolAddress((void**)&W216,    d_W216);
    cudaGetSymbolAddress((void**)&e16,     d_emb16);
    cudaGetSymbolAddress((void**)&Ac,      d_A);
    cudaGetSymbolAddress((void**)&Qc,      d_Q);
    cudaGetSymbolAddress((void**)&tQc,     d_tQ);
    cudaGetSymbolAddress((void**)&maxQp,   d_maxQp);
    cudaGetSymbolAddress((void**)&maxA,    d_maxA);

    cudaFuncSetAttribute(conv_all, cudaFuncAttributeMaxDynamicSharedMemorySize, SMEM_ALL);

    const int prepBlocks = (3 * Fp * EPW + 255) / 256;
    prep_w<<<prepBlocks, 256>>>(conv_w, conv_b, biasPad, W16);
    prep_w2<<<prepBlocks, 256>>>(U, conv_b, conv_w, b2, W216);
    emb_cvt<<<(NEMBP + 255) / 256, 256>>>(emb, e16);

    dim3 gC(6, Fp / 128, Bn);   // x: 0-3 = A-tiles; 4 = Q; 5 = tQ
    conv_all<<<gC, 256, SMEM_ALL>>>(question, answer, e16, W16, W216,
                                    biasPad, b2, Ac, Qc, tQc);

    dim3 gG(4, Bn);
    g_mma<<<gG, 256>>>(tQc, Ac, maxQp, maxA);
    final_kernel<<<Bn, 256>>>(Qc, Ac, maxQp, maxA, out);
}